// round 12
// baseline (speedup 1.0000x reference)
#include <cuda_runtime.h>
#include <cstdint>

#define NN 50000
#define EE 800000
#define IND 16
#define H 64
#define EAD 8

#define GRID_P 148

__device__ float g_h[NN * H];
__device__ float g_agg[NN * H];
__device__ uint32_t g_hh2[NN * 32];
__device__ uint32_t g_hl2[NN * 32];
__device__ float g_PQ[NN * 128];
__device__ float g_P1[NN * 256];
__device__ float g_R[EE * 64];
__device__ float g_R1[EE * 128];

__device__ uint32_t g_Wu_h[32 * 136],  g_Wu_l[32 * 136];
__device__ uint32_t g_W2_h[32 * 136],  g_W2_l[32 * 136];
__device__ uint32_t g_Wpm_h[16 * 256], g_Wpm_l[16 * 256];
__device__ uint32_t g_Wpe_h[16 * 512], g_Wpe_l[16 * 512];

// ---------------------------------------------------------------------------
__device__ __forceinline__ void splitpack(float a0, float a1, uint32_t& hi, uint32_t& lo) {
    uint32_t h, l;
    asm("cvt.rn.bf16x2.f32 %0, %1, %2;" : "=r"(h) : "f"(a1), "f"(a0));
    float r0 = a0 - __uint_as_float(h << 16);
    float r1 = a1 - __uint_as_float(h & 0xFFFF0000u);
    asm("cvt.rn.bf16x2.f32 %0, %1, %2;" : "=r"(l) : "f"(r1), "f"(r0));
    hi = h; lo = l;
}

__device__ __forceinline__ void mma_bf16(float* c, const uint32_t* a, uint32_t b0, uint32_t b1) {
    asm volatile(
        "mma.sync.aligned.m16n8k16.row.col.f32.bf16.bf16.f32 "
        "{%0,%1,%2,%3}, {%4,%5,%6,%7}, {%8,%9}, {%0,%1,%2,%3};"
        : "+f"(c[0]), "+f"(c[1]), "+f"(c[2]), "+f"(c[3])
        : "r"(a[0]), "r"(a[1]), "r"(a[2]), "r"(a[3]), "r"(b0), "r"(b1));
}

#define CP_ASYNC16(saddr, gptr) \
    asm volatile("cp.async.cg.shared.global [%0], [%1], 16;" :: "r"(saddr), "l"(gptr) : "memory")
#define CP_COMMIT() asm volatile("cp.async.commit_group;" ::: "memory")
#define CP_WAIT1()  asm volatile("cp.async.wait_group 1;" ::: "memory")

__device__ __forceinline__ int hpack_idx(int p) {
    int s = p >> 3, r = p & 7;
    return (r < 4) ? (s * 4 + r) * 2 : (s * 4 + r - 4) * 2 + 1;
}

// ---------------------------------------------------------------------------
__device__ __forceinline__ void emit_w(const float* W, int Kp, int N, int RS,
                                       uint32_t* oh, uint32_t* ol, int i) {
    int row = i / N, n = i - row * N;
    int s = row >> 2, j = row & 3;
    int kp1 = 8 * s + j, kp2 = kp1 + 4;
    float a0 = 0.f, a1 = 0.f, c0 = 0.f, c1 = 0.f;
    if (kp1 < Kp) { a0 = W[(2 * kp1) * N + n]; a1 = W[(2 * kp1 + 1) * N + n]; }
    if (kp2 < Kp) { c0 = W[(2 * kp2) * N + n]; c1 = W[(2 * kp2 + 1) * N + n]; }
    uint32_t h1, l1, h2, l2;
    splitpack(a0, a1, h1, l1);
    splitpack(c0, c1, h2, l2);
    oh[row * RS + 2 * n] = h1; oh[row * RS + 2 * n + 1] = h2;
    ol[row * RS + 2 * n] = l1; ol[row * RS + 2 * n + 1] = l2;
}

__device__ __forceinline__ float cat_msg(const float* Wm, int k, int n) {
    return (n < 64) ? Wm[k * 64 + n] : Wm[(64 + k) * 64 + (n - 64)];
}
__device__ __forceinline__ float cat_eh(const float* W1, int k, int n) {
    return (n < 128) ? W1[k * 128 + n] : W1[(64 + k) * 128 + (n - 128)];
}

#define SW_U  (32*64)
#define SW_2  (32*64)
#define SW_PM (16*128)
#define SW_PE (16*256)
#define SW_TOTAL (SW_U + SW_2 + SW_PM + SW_PE)

__global__ void split_w_kernel(const float* __restrict__ Wu, const float* __restrict__ W2,
                               const float* __restrict__ Wm, const float* __restrict__ W1) {
    int i = blockIdx.x * 256 + threadIdx.x;
    if (i < SW_U) { emit_w(Wu, 64, 64, 136, g_Wu_h, g_Wu_l, i); return; }
    i -= SW_U;
    if (i < SW_2) { emit_w(W2, 64, 64, 136, g_W2_h, g_W2_l, i); return; }
    i -= SW_2;
    if (i < SW_PM) {
        int row = i >> 7, n = i & 127;
        int s = row >> 2, j = row & 3;
        int kp1 = 8 * s + j, kp2 = kp1 + 4;
        uint32_t h1, l1, h2, l2;
        splitpack(cat_msg(Wm, 2 * kp1, n), cat_msg(Wm, 2 * kp1 + 1, n), h1, l1);
        splitpack(cat_msg(Wm, 2 * kp2, n), cat_msg(Wm, 2 * kp2 + 1, n), h2, l2);
        g_Wpm_h[row * 256 + 2 * n] = h1; g_Wpm_h[row * 256 + 2 * n + 1] = h2;
        g_Wpm_l[row * 256 + 2 * n] = l1; g_Wpm_l[row * 256 + 2 * n + 1] = l2;
        return;
    }
    i -= SW_PM;
    if (i < SW_PE) {
        int row = i >> 8, n = i & 255;
        int s = row >> 2, j = row & 3;
        int kp1 = 8 * s + j, kp2 = kp1 + 4;
        uint32_t h1, l1, h2, l2;
        splitpack(cat_eh(W1, 2 * kp1, n), cat_eh(W1, 2 * kp1 + 1, n), h1, l1);
        splitpack(cat_eh(W1, 2 * kp2, n), cat_eh(W1, 2 * kp2 + 1, n), h2, l2);
        g_Wpe_h[row * 512 + 2 * n] = h1; g_Wpe_h[row * 512 + 2 * n + 1] = h2;
        g_Wpe_l[row * 512 + 2 * n] = l1; g_Wpe_l[row * 512 + 2 * n + 1] = l2;
    }
}

__global__ void zero_agg_kernel() {
    int i = blockIdx.x * 256 + threadIdx.x;
    if (i < NN * H) g_agg[i] = 0.f;
}

__global__ void compR_kernel(const float* __restrict__ ea,
                             const float* __restrict__ Wm, const float* __restrict__ bm) {
    __shared__ float Wb[8 * 64];
    __shared__ float bs[64];
    for (int i = threadIdx.x; i < 512; i += 256) Wb[i] = Wm[(128 + (i >> 6)) * 64 + (i & 63)];
    if (threadIdx.x < 64) bs[threadIdx.x] = bm[threadIdx.x];
    __syncthreads();
    int idx = blockIdx.x * 256 + threadIdx.x;
    int e = idx >> 4, c = (idx & 15) * 4;
    float4 r = make_float4(bs[c], bs[c + 1], bs[c + 2], bs[c + 3]);
#pragma unroll
    for (int k = 0; k < 8; k++) {
        float a = ea[e * 8 + k];
        r.x += a * Wb[k * 64 + c];
        r.y += a * Wb[k * 64 + c + 1];
        r.z += a * Wb[k * 64 + c + 2];
        r.w += a * Wb[k * 64 + c + 3];
    }
    *(float4*)(g_R + (size_t)e * 64 + c) = r;
}

__global__ void compR1_kernel(const float* __restrict__ ea,
                              const float* __restrict__ W1, const float* __restrict__ b1) {
    __shared__ float Wb[8 * 128];
    __shared__ float bs[128];
    for (int i = threadIdx.x; i < 1024; i += 256) Wb[i] = W1[(128 + (i >> 7)) * 128 + (i & 127)];
    for (int i = threadIdx.x; i < 128; i += 256) bs[i] = b1[i];
    __syncthreads();
    int idx = blockIdx.x * 256 + threadIdx.x;
    int e = idx >> 5, c = (idx & 31) * 4;
    float4 r = make_float4(bs[c], bs[c + 1], bs[c + 2], bs[c + 3]);
#pragma unroll
    for (int k = 0; k < 8; k++) {
        float a = ea[e * 8 + k];
        r.x += a * Wb[k * 128 + c];
        r.y += a * Wb[k * 128 + c + 1];
        r.z += a * Wb[k * 128 + c + 2];
        r.w += a * Wb[k * 128 + c + 3];
    }
    *(float4*)(g_R1 + (size_t)e * 128 + c) = r;
}

// ---------------------------------------------------------------------------
__global__ void enc_kernel(const float* __restrict__ x,
                           const float* __restrict__ W,
                           const float* __restrict__ b) {
    __shared__ float Ws[IND * H];
    __shared__ float bs[H];
    for (int i = threadIdx.x; i < IND * H; i += blockDim.x) Ws[i] = W[i];
    if (threadIdx.x < H) bs[threadIdx.x] = b[threadIdx.x];
    __syncthreads();
    int node = blockIdx.x * blockDim.x + threadIdx.x;
    if (node >= NN) return;
    float xv[IND];
#pragma unroll
    for (int k = 0; k < IND; k++) xv[k] = x[node * IND + k];
#pragma unroll 4
    for (int n = 0; n < H; n += 2) {
        float a0 = bs[n], a1 = bs[n + 1];
#pragma unroll
        for (int k = 0; k < IND; k++) {
            a0 += xv[k] * Ws[k * H + n];
            a1 += xv[k] * Ws[k * H + n + 1];
        }
        g_h[node * H + n] = a0;
        g_h[node * H + n + 1] = a1;
        uint32_t h, l;
        splitpack(a0, a1, h, l);
        int idx = hpack_idx(n >> 1);
        g_hh2[node * 32 + idx] = h;
        g_hl2[node * 32 + idx] = l;
    }
}

// ---------------------------------------------------------------------------
// proj: out[node][blockIdx.y*128 .. +128) = h_packed @ Wcat-block (K=64)
// which=0 -> g_Wpm (rs2=128, out g_PQ); which=1 -> g_Wpe (rs2=256, out g_P1)
// ---------------------------------------------------------------------------
#define HSTR 20

__global__ void __launch_bounds__(256, 1)
proj_kernel(int which) {
    __shared__ uint2 sh[2 * 64 * HSTR];
    uint2* Ah = sh;
    uint2* Al = sh + 64 * HSTR;
    const uint2* Wh2 = which ? (const uint2*)g_Wpe_h : (const uint2*)g_Wpm_h;
    const uint2* Wl2 = which ? (const uint2*)g_Wpe_l : (const uint2*)g_Wpm_l;
    float* outp = which ? g_P1 : g_PQ;
    const int rs2 = which ? 256 : 128;
    const int ld = rs2;
    const int nbase = blockIdx.x * 64;
    const int colbase = blockIdx.y * 128;
    const int tid = threadIdx.x;
    const int lane = tid & 31, warp = tid >> 5;
    const int g = lane >> 2, tig = lane & 3;
    const int warpM = warp & 3, warpN = warp >> 2;
    const int row0 = warpM * 16 + g;

    uint2 brh[4][8], brl[4][8];
#pragma unroll
    for (int s = 0; s < 4; s++)
#pragma unroll
        for (int nt = 0; nt < 8; nt++) {
            int idx = (s * 4 + tig) * rs2 + colbase + warpN * 64 + nt * 8 + g;
            brh[s][nt] = __ldg(Wh2 + idx);
            brl[s][nt] = __ldg(Wl2 + idx);
        }
    for (int i = tid; i < 64 * 16; i += 256) {
        int nd = i >> 4, u = i & 15;
        int gn = nbase + nd;
        uint2 h = make_uint2(0, 0), l = make_uint2(0, 0);
        if (gn < NN) {
            h = ((const uint2*)g_hh2)[gn * 16 + u];
            l = ((const uint2*)g_hl2)[gn * 16 + u];
        }
        Ah[nd * HSTR + u] = h;
        Al[nd * HSTR + u] = l;
    }
    __syncthreads();

    float acc[8][4] = {};
#pragma unroll
    for (int s = 0; s < 4; s++) {
        uint2 u0h = Ah[ row0      * HSTR + s * 4 + tig];
        uint2 u1h = Ah[(row0 + 8) * HSTR + s * 4 + tig];
        uint2 u0l = Al[ row0      * HSTR + s * 4 + tig];
        uint2 u1l = Al[(row0 + 8) * HSTR + s * 4 + tig];
        uint32_t ah[4] = {u0h.x, u1h.x, u0h.y, u1h.y};
        uint32_t al[4] = {u0l.x, u1l.x, u0l.y, u1l.y};
#pragma unroll
        for (int nt = 0; nt < 8; nt++) {
            mma_bf16(acc[nt], ah, brh[s][nt].x, brh[s][nt].y);
            mma_bf16(acc[nt], al, brh[s][nt].x, brh[s][nt].y);
            mma_bf16(acc[nt], ah, brl[s][nt].x, brl[s][nt].y);
        }
    }
    const int gn0 = nbase + row0, gn1 = gn0 + 8;
#pragma unroll
    for (int nt = 0; nt < 8; nt++) {
        int n = colbase + warpN * 64 + nt * 8 + 2 * tig;
        if (gn0 < NN) *(float2*)(outp + (size_t)gn0 * ld + n) = make_float2(acc[nt][0], acc[nt][1]);
        if (gn1 < NN) *(float2*)(outp + (size_t)gn1 * ld + n) = make_float2(acc[nt][2], acc[nt][3]);
    }
}

// ---------------------------------------------------------------------------
// msg edge pass
// ---------------------------------------------------------------------------
__global__ void __launch_bounds__(256)
edgepass_kernel(const int* __restrict__ ei) {
    int idx = blockIdx.x * 256 + threadIdx.x;
    int e = idx >> 2, q = idx & 3;
    int s = ei[e], d = ei[EE + e];
    const float4* P = (const float4*)(g_PQ + (size_t)s * 128 + q * 16);
    const float4* Q = (const float4*)(g_PQ + (size_t)d * 128 + 64 + q * 16);
    const float4* R = (const float4*)(g_R + (size_t)e * 64 + q * 16);
    float* o = g_agg + d * 64 + q * 16;
#pragma unroll
    for (int j = 0; j < 4; j++) {
        float4 p = P[j], qq = Q[j], r = R[j];
        float4 v = make_float4(fmaxf(p.x + qq.x + r.x, 0.f),
                               fmaxf(p.y + qq.y + r.y, 0.f),
                               fmaxf(p.z + qq.z + r.z, 0.f),
                               fmaxf(p.w + qq.w + r.w, 0.f));
        asm volatile("red.global.add.v4.f32 [%0], {%1,%2,%3,%4};"
                     :: "l"(o + 4 * j), "f"(v.x), "f"(v.y), "f"(v.z), "f"(v.w) : "memory");
    }
}

// ---------------------------------------------------------------------------
// Update (unchanged): h = relu([h|agg]@Wu + b); zeroes g_agg.
// ---------------------------------------------------------------------------
#define ASLOT 36
#define UPD_SMEM (2 * 64 * ASLOT * 8)

__global__ void __launch_bounds__(256, 1)
upd_kernel(const float* __restrict__ bias) {
    extern __shared__ uint2 smU[];
    uint2* Ah = smU;
    uint2* Al = smU + 64 * ASLOT;
    const int nbase = blockIdx.x * 64;
    const int tid = threadIdx.x;
    const int lane = tid & 31, warp = tid >> 5;
    const int g = lane >> 2, tig = lane & 3;
    const int warpM = warp & 3, warpN = warp >> 2;
    const int row0 = warpM * 16 + g;

    uint2 brh[8][4], brl[8][4];
    const uint2* WuH = (const uint2*)g_Wu_h;
    const uint2* WuL = (const uint2*)g_Wu_l;
#pragma unroll
    for (int s = 0; s < 8; s++)
#pragma unroll
        for (int nt = 0; nt < 4; nt++) {
            int idx = (s * 4 + tig) * 68 + warpN * 32 + nt * 8 + g;
            brh[s][nt] = WuH[idx];
            brl[s][nt] = WuL[idx];
        }

    for (int i = tid; i < 64 * 32; i += 256) {
        int nd = i >> 5, u = i & 31;
        int gn = nbase + nd;
        if (u < 16) {
            uint2 h = make_uint2(0, 0), l = make_uint2(0, 0);
            if (gn < NN) {
                h = ((const uint2*)g_hh2)[gn * 16 + u];
                l = ((const uint2*)g_hl2)[gn * 16 + u];
            }
            Ah[nd * ASLOT + u] = h;
            Al[nd * ASLOT + u] = l;
        } else {
            int s = u >> 2, j = u & 3;
            int pa1 = 8 * (s - 4) + j, pa2 = pa1 + 4;
            uint32_t h1 = 0, l1 = 0, h2 = 0, l2 = 0;
            if (gn < NN) {
                float2 v1 = *(float2*)(g_agg + gn * H + 2 * pa1);
                float2 v2 = *(float2*)(g_agg + gn * H + 2 * pa2);
                splitpack(v1.x, v1.y, h1, l1);
                splitpack(v2.x, v2.y, h2, l2);
                *(float2*)(g_agg + gn * H + 2 * pa1) = make_float2(0.f, 0.f);
                *(float2*)(g_agg + gn * H + 2 * pa2) = make_float2(0.f, 0.f);
            }
            Ah[nd * ASLOT + u] = make_uint2(h1, h2);
            Al[nd * ASLOT + u] = make_uint2(l1, l2);
        }
    }
    __syncthreads();

    float acc[4][4] = {};
#pragma unroll
    for (int s = 0; s < 8; s++) {
        uint2 u0h = Ah[ row0      * ASLOT + s * 4 + tig];
        uint2 u1h = Ah[(row0 + 8) * ASLOT + s * 4 + tig];
        uint2 u0l = Al[ row0      * ASLOT + s * 4 + tig];
        uint2 u1l = Al[(row0 + 8) * ASLOT + s * 4 + tig];
        uint32_t ah[4] = {u0h.x, u1h.x, u0h.y, u1h.y};
        uint32_t al[4] = {u0l.x, u1l.x, u0l.y, u1l.y};
#pragma unroll
        for (int nt = 0; nt < 4; nt++) {
            mma_bf16(acc[nt], ah, brh[s][nt].x, brh[s][nt].y);
            mma_bf16(acc[nt], al, brh[s][nt].x, brh[s][nt].y);
            mma_bf16(acc[nt], ah, brl[s][nt].x, brl[s][nt].y);
        }
    }

    const int gn0 = nbase + row0, gn1 = nbase + row0 + 8;
#pragma unroll
    for (int nt = 0; nt < 4; nt++) {
        int n = warpN * 32 + nt * 8 + 2 * tig;
        int p = n >> 1;
        int idx = hpack_idx(p);
        float bb0 = __ldg(bias + n), bb1 = __ldg(bias + n + 1);
        if (gn0 < NN) {
            float v0 = fmaxf(acc[nt][0] + bb0, 0.f);
            float v1 = fmaxf(acc[nt][1] + bb1, 0.f);
            *(float2*)(g_h + gn0 * H + n) = make_float2(v0, v1);
            splitpack(v0, v1, g_hh2[gn0 * 32 + idx], g_hl2[gn0 * 32 + idx]);
        }
        if (gn1 < NN) {
            float v0 = fmaxf(acc[nt][2] + bb0, 0.f);
            float v1 = fmaxf(acc[nt][3] + bb1, 0.f);
            *(float2*)(g_h + gn1 * H + n) = make_float2(v0, v1);
            splitpack(v0, v1, g_hh2[gn1 * 32 + idx], g_hl2[gn1 * 32 + idx]);
        }
    }
}

// ---------------------------------------------------------------------------
// Node head (unchanged)
// ---------------------------------------------------------------------------
__global__ void __launch_bounds__(256)
nodehead_kernel(const float* __restrict__ W1, const float* __restrict__ b1,
                const float* __restrict__ W2, const float* __restrict__ b2,
                float* __restrict__ out) {
    __shared__ float As[64 * 64];
    __shared__ float Ws[64 * 64];
    __shared__ float W2s[64 * 2];
    __shared__ float b2s[2];
    int nbase = blockIdx.x * 64;

    for (int i = threadIdx.x; i < 64 * 64; i += 256) Ws[i] = W1[i];
    if (threadIdx.x < 128) W2s[threadIdx.x] = W2[threadIdx.x];
    if (threadIdx.x < 2) b2s[threadIdx.x] = b2[threadIdx.x];
    for (int i = threadIdx.x; i < 64 * 64; i += 256) {
        int nd = i >> 6, k = i & 63;
        int gn = nbase + nd;
        As[i] = (gn < NN) ? g_h[gn * H + k] : 0.f;
    }
    __syncthreads();

    int tn = threadIdx.x & 15, te = threadIdx.x >> 4;
    float acc[4][4] = {};
    for (int k = 0; k < 64; k += 4) {
        float4 av4[4];
#pragma unroll
        for (int i = 0; i < 4; i++)
            av4[i] = *(const float4*)(As + (te * 4 + i) * 64 + k);
        const float* av = (const float*)av4;
#pragma unroll
        for (int kk = 0; kk < 4; kk++) {
            float4 w = *(const float4*)(Ws + (k + kk) * H + tn * 4);
#pragma unroll
            for (int i = 0; i < 4; i++) {
                float a = av[i * 4 + kk];
                acc[i][0] += a * w.x;
                acc[i][1] += a * w.y;
                acc[i][2] += a * w.z;
                acc[i][3] += a * w.w;
            }
        }
    }
    __syncthreads();

    float4 bvv = *(const float4*)(b1 + tn * 4);
    const float* bvp = (const float*)&bvv;
#pragma unroll
    for (int i = 0; i < 4; i++)
#pragma unroll
        for (int j = 0; j < 4; j++)
            As[(tn * 4 + j) * 64 + te * 4 + i] = fmaxf(acc[i][j] + bvp[j], 0.f);
    __syncthreads();

    if (threadIdx.x < 128) {
        int nd = threadIdx.x & 63, j = threadIdx.x >> 6;
        int gn = nbase + nd;
        if (gn < NN) {
            float s = b2s[j];
#pragma unroll 8
            for (int k = 0; k < 64; k++) s += As[k * 64 + nd] * W2s[k * 2 + j];
            out[gn * 2 + j] = s;
        }
    }
}

// ---------------------------------------------------------------------------
// Edge head v2: persistent, 64-edge tiles, double-buffered fp32 staging of
// P1[src] / Q1[dst] / R1[e]; C1 split-packed in place; GEMM2 (W2 regs) + GEMM3.
// Row layout (floats): [0,128) P, [136,264) Q, [272,400) R1; stride 408.
// ---------------------------------------------------------------------------
#define SROW 408
#define BUFW (64 * SROW)
#define NT_EH (EE / 64)
#define EH_SMEM (2 * BUFW * 4 + 390 * 4)   // 210456 B

__device__ __forceinline__ void stage_eh(float* Sb,
        const int* __restrict__ src, const int* __restrict__ dst,
        int tbase, int tid) {
    int e = tid >> 2, sub = tid & 3;
    int ge = tbase + e;
    uint32_t rb = (uint32_t)__cvta_generic_to_shared(Sb + e * SROW);
    const float* p;
    uint32_t ofs;
    if (sub == 0)      { p = g_P1 + (size_t)src[ge] * 256;        ofs = 0; }
    else if (sub == 1) { p = g_P1 + (size_t)src[ge] * 256 + 64;   ofs = 256; }
    else if (sub == 2) { p = g_P1 + (size_t)dst[ge] * 256 + 128;  ofs = 544; }
    else               { p = g_P1 + (size_t)dst[ge] * 256 + 192;  ofs = 800; }
#pragma unroll
    for (int j = 0; j < 16; j++) CP_ASYNC16(rb + ofs + j * 16, p + j * 4);
    const float* r = g_R1 + (size_t)ge * 128 + 32 * sub;
#pragma unroll
    for (int j = 0; j < 8; j++) CP_ASYNC16(rb + 1088 + 128 * sub + j * 16, r + j * 4);
}

__global__ void __launch_bounds__(256, 1)
edgehead_kernel(const int* __restrict__ ei,
                const float* __restrict__ b2,
                const float* __restrict__ W3, const float* __restrict__ b3,
                float* __restrict__ out) {
    extern __shared__ float smF[];
    float* W3s = smF + 2 * BUFW;
    float* b3s = W3s + 384;
    const int* src = ei;
    const int* dst = ei + EE;
    const int tid = threadIdx.x;

    for (int i = tid; i < 384; i += 256) W3s[i] = W3[i];
    if (tid < 6) b3s[tid] = b3[tid];

    const int lane = tid & 31, warp = tid >> 5;
    const int g = lane >> 2, tig = lane & 3;
    const int warpM = warp & 3, warpN = warp >> 2;
    const int row0 = warpM * 16 + g;

    uint2 brh[8][4], brl[8][4];
    const uint2* W2H = (const uint2*)g_W2_h;
    const uint2* W2L = (const uint2*)g_W2_l;
#pragma unroll
    for (int s = 0; s < 8; s++)
#pragma unroll
        for (int nt = 0; nt < 4; nt++) {
            int idx = (s * 4 + tig) * 68 + warpN * 32 + nt * 8 + g;
            brh[s][nt] = W2H[idx];
            brl[s][nt] = W2L[idx];
        }
    float2 b2v[4];
#pragma unroll
    for (int nt = 0; nt < 4; nt++) {
        int n = warpN * 32 + nt * 8 + 2 * tig;
        b2v[nt] = make_float2(__ldg(b2 + n), __ldg(b2 + n + 1));
    }
    __syncthreads();

    int t = blockIdx.x, cur = 0;
    if (t < NT_EH) stage_eh(smF, src, dst, t * 64, tid);
    CP_COMMIT();

    const int e = tid >> 2, q = tid & 3;
    const int off0 = (q == 0) ? 0 : (q == 1) ? 4 : (q == 2) ? 1 : 5;
    const int off1 = off0 + 2;

    for (; t < NT_EH; t += GRID_P) {
        int tn = t + GRID_P;
        if (tn < NT_EH) stage_eh(smF + (cur ^ 1) * BUFW, src, dst, tn * 64, tid);
        CP_COMMIT();
        CP_WAIT1();
        __syncthreads();

        float* Sb = smF + cur * BUFW;
        const int ebase = t * 64;

        // phase 1: C1 = relu(P+Q+R1) -> regs, split-packed
        uint32_t c1h[16], c1l[16];
        {
            const float* base = Sb + e * SROW;
#pragma unroll
            for (int j = 0; j < 8; j++) {
                int c = 4 * q + 16 * j;
                float4 p  = *(const float4*)(base + c);
                float4 qq = *(const float4*)(base + 136 + c);
                float4 r  = *(const float4*)(base + 272 + c);
                float v0 = fmaxf(p.x + qq.x + r.x, 0.f);
                float v1 = fmaxf(p.y + qq.y + r.y, 0.f);
                float v2 = fmaxf(p.z + qq.z + r.z, 0.f);
                float v3 = fmaxf(p.w + qq.w + r.w, 0.f);
                splitpack(v0, v1, c1h[2 * j], c1l[2 * j]);
                splitpack(v2, v3, c1h[2 * j + 1], c1l[2 * j + 1]);
            }
        }
        __syncthreads();

        // phase 2: write C1 planes (u32 stride 72)
        {
            uint32_t* bh = (uint32_t*)Sb + e * 72;
            uint32_t* bl = (uint32_t*)Sb + 64 * 72 + e * 72;
#pragma unroll
            for (int j = 0; j < 8; j++) {
                bh[8 * j + off0] = c1h[2 * j];
                bh[8 * j + off1] = c1h[2 * j + 1];
                bl[8 * j + off0] = c1l[2 * j];
                bl[8 * j + off1] = c1l[2 * j + 1];
            }
        }
        __syncthreads();

        // phase 3: GEMM2 (bf16x3, W2 regs)
        const uint2* Ch2 = (const uint2*)Sb;
        const uint2* Cl2 = Ch2 + 64 * 36;
        float acc2[4][4] = {};
#pragma unroll
        for (int s = 0; s < 8; s++) {
            uint2 u0h = Ch2[ row0      * 36 + s * 4 + tig];
            uint2 u1h = Ch2[(row0 + 8) * 36 + s * 4 + tig];
            uint2 u0l = Cl2[ row0      * 36 + s * 4 + tig];
            uint2 u1l = Cl2[(row0 + 8) * 36 + s * 4 + tig];
            uint32_t ah[4] = {u0h.x, u1h.x, u0h.y, u1h.y};
            uint32_t al[4] = {u0l.x, u1l.x, u0l.y, u1l.y};
#pragma unroll
            for (int nt = 0; nt < 4; nt++) {
                mma_bf16(acc2[nt], ah, brh[s][nt].x, brh[s][nt].y);
                mma_bf16(acc2[nt], al, brh[s][nt].x, brh[s][nt].y);
                mma_bf16(acc2[nt], ah, brl[s][nt].x, brl[s][nt].y);
            }
        }

        // epilogue2: C2 fp32 [64][65] at word 9216 (disjoint from C1 region)
        float* C2 = Sb + 9216;
#pragma unroll
        for (int nt = 0; nt < 4; nt++) {
            int n = warpN * 32 + nt * 8 + 2 * tig;
            C2[ row0      * 65 + n    ] = fmaxf(acc2[nt][0] + b2v[nt].x, 0.f);
            C2[ row0      * 65 + n + 1] = fmaxf(acc2[nt][1] + b2v[nt].y, 0.f);
            C2[(row0 + 8) * 65 + n    ] = fmaxf(acc2[nt][2] + b2v[nt].x, 0.f);
            C2[(row0 + 8) * 65 + n + 1] = fmaxf(acc2[nt][3] + b2v[nt].y, 0.f);
        }
        __syncthreads();

        // GEMM3
        for (int w = tid; w < 384; w += 256) {
            int ee = w & 63, j = w >> 6;
            float s = b3s[j];
#pragma unroll 8
            for (int k = 0; k < 64; k++) s += C2[ee * 65 + k] * W3s[k * 6 + j];
            out[(ebase + ee) * 6 + j] = s;
        }
        __syncthreads();
        cur ^= 1;
    }
}

// ---------------------------------------------------------------------------

extern "C" void kernel_launch(void* const* d_in, const int* in_sizes, int n_in,
                              void* d_out, int out_size) {
    const float* x     = (const float*)d_in[0];
    const int*   ei    = (const int*)d_in[1];
    const float* ea    = (const float*)d_in[2];
    const float* W_enc = (const float*)d_in[3];
    const float* b_enc = (const float*)d_in[4];
    const float* W_msg = (const float*)d_in[5];
    const float* b_msg = (const float*)d_in[6];
    const float* W_upd = (const float*)d_in[7];
    const float* b_upd = (const float*)d_in[8];
    const float* W_nd1 = (const float*)d_in[9];
    const float* b_nd1 = (const float*)d_in[10];
    const float* W_nd2 = (const float*)d_in[11];
    const float* b_nd2 = (const float*)d_in[12];
    const float* W_ed1 = (const float*)d_in[13];
    const float* b_ed1 = (const float*)d_in[14];
    const float* W_ed2 = (const float*)d_in[15];
    const float* b_ed2 = (const float*)d_in[16];
    const float* W_ed3 = (const float*)d_in[17];
    const float* b_ed3 = (const float*)d_in[18];
    float* out = (float*)d_out;

    cudaFuncSetAttribute(upd_kernel, cudaFuncAttributeMaxDynamicSharedMemorySize, UPD_SMEM);
    cudaFuncSetAttribute(edgehead_kernel, cudaFuncAttributeMaxDynamicSharedMemorySize, EH_SMEM);

    split_w_kernel<<<(SW_TOTAL + 255) / 256, 256>>>(W_upd, W_ed2, W_msg, W_ed1);
    zero_agg_kernel<<<(NN * H + 255) / 256, 256>>>();
    compR_kernel<<<EE * 16 / 256, 256>>>(ea, W_msg, b_msg);
    compR1_kernel<<<EE * 32 / 256, 256>>>(ea, W_ed1, b_ed1);
    enc_kernel<<<(NN + 255) / 256, 256>>>(x, W_enc, b_enc);

    dim3 pgm((NN + 63) / 64, 1);
    proj_kernel<<<pgm, 256>>>(0);                       // PQ from encoder h
    for (int l = 0; l < 3; l++) {
        edgepass_kernel<<<EE * 4 / 256, 256>>>(ei);     // agg += relu(P+Q+R)
        upd_kernel<<<(NN + 63) / 64, 256, UPD_SMEM>>>(b_upd);
        if (l < 2) proj_kernel<<<pgm, 256>>>(0);        // PQ from new h
    }
    nodehead_kernel<<<(NN + 63) / 64, 256>>>(W_nd1, b_nd1, W_nd2, b_nd2, out);
    dim3 pge((NN + 63) / 64, 2);
    proj_kernel<<<pge, 256>>>(1);                       // P1 from final h
    edgehead_kernel<<<GRID_P, 256, EH_SMEM>>>(ei, b_ed2, W_ed3, b_ed3, out + 2 * NN);
}

// round 14
// speedup vs baseline: 1.0506x; 1.0506x over previous
#include <cuda_runtime.h>
#include <cstdint>

#define NN 50000
#define EE 800000
#define IND 16
#define H 64
#define EAD 8

#define GRID_P 148

__device__ float g_h[NN * H];
__device__ float g_agg[NN * H];        // zero-init; re-zeroed by every upd round
__device__ uint32_t g_hh2[NN * 32];
__device__ uint32_t g_hl2[NN * 32];
__device__ float g_PQ[NN * 128];
__device__ float g_P1[NN * 256];

__device__ uint32_t g_Wu_h[32 * 136],  g_Wu_l[32 * 136];
__device__ uint32_t g_W2_h[32 * 136],  g_W2_l[32 * 136];
__device__ uint32_t g_Wpm_h[16 * 256], g_Wpm_l[16 * 256];
__device__ uint32_t g_Wpe_h[16 * 512], g_Wpe_l[16 * 512];

// ---------------------------------------------------------------------------
__device__ __forceinline__ void splitpack(float a0, float a1, uint32_t& hi, uint32_t& lo) {
    uint32_t h, l;
    asm("cvt.rn.bf16x2.f32 %0, %1, %2;" : "=r"(h) : "f"(a1), "f"(a0));
    float r0 = a0 - __uint_as_float(h << 16);
    float r1 = a1 - __uint_as_float(h & 0xFFFF0000u);
    asm("cvt.rn.bf16x2.f32 %0, %1, %2;" : "=r"(l) : "f"(r1), "f"(r0));
    hi = h; lo = l;
}

__device__ __forceinline__ void mma_bf16(float* c, const uint32_t* a, uint32_t b0, uint32_t b1) {
    asm volatile(
        "mma.sync.aligned.m16n8k16.row.col.f32.bf16.bf16.f32 "
        "{%0,%1,%2,%3}, {%4,%5,%6,%7}, {%8,%9}, {%0,%1,%2,%3};"
        : "+f"(c[0]), "+f"(c[1]), "+f"(c[2]), "+f"(c[3])
        : "r"(a[0]), "r"(a[1]), "r"(a[2]), "r"(a[3]), "r"(b0), "r"(b1));
}

#define CP_ASYNC16(saddr, gptr) \
    asm volatile("cp.async.cg.shared.global [%0], [%1], 16;" :: "r"(saddr), "l"(gptr) : "memory")
#define CP_COMMIT() asm volatile("cp.async.commit_group;" ::: "memory")
#define CP_WAIT1()  asm volatile("cp.async.wait_group 1;" ::: "memory")

__device__ __forceinline__ int hpack_idx(int p) {
    int s = p >> 3, r = p & 7;
    return (r < 4) ? (s * 4 + r) * 2 : (s * 4 + r - 4) * 2 + 1;
}

// ---------------------------------------------------------------------------
__device__ __forceinline__ void emit_w(const float* W, int Kp, int N, int RS,
                                       uint32_t* oh, uint32_t* ol, int i) {
    int row = i / N, n = i - row * N;
    int s = row >> 2, j = row & 3;
    int kp1 = 8 * s + j, kp2 = kp1 + 4;
    float a0 = 0.f, a1 = 0.f, c0 = 0.f, c1 = 0.f;
    if (kp1 < Kp) { a0 = W[(2 * kp1) * N + n]; a1 = W[(2 * kp1 + 1) * N + n]; }
    if (kp2 < Kp) { c0 = W[(2 * kp2) * N + n]; c1 = W[(2 * kp2 + 1) * N + n]; }
    uint32_t h1, l1, h2, l2;
    splitpack(a0, a1, h1, l1);
    splitpack(c0, c1, h2, l2);
    oh[row * RS + 2 * n] = h1; oh[row * RS + 2 * n + 1] = h2;
    ol[row * RS + 2 * n] = l1; ol[row * RS + 2 * n + 1] = l2;
}

__device__ __forceinline__ float cat_msg(const float* Wm, int k, int n) {
    return (n < 64) ? Wm[k * 64 + n] : Wm[(64 + k) * 64 + (n - 64)];
}
__device__ __forceinline__ float cat_eh(const float* W1, int k, int n) {
    return (n < 128) ? W1[k * 128 + n] : W1[(64 + k) * 128 + (n - 128)];
}

#define SW_U  (32*64)
#define SW_2  (32*64)
#define SW_PM (16*128)
#define SW_PE (16*256)
#define SW_TOTAL (SW_U + SW_2 + SW_PM + SW_PE)

__global__ void split_w_kernel(const float* __restrict__ Wu, const float* __restrict__ W2,
                               const float* __restrict__ Wm, const float* __restrict__ W1) {
    int i = blockIdx.x * 256 + threadIdx.x;
    if (i < SW_U) { emit_w(Wu, 64, 64, 136, g_Wu_h, g_Wu_l, i); return; }
    i -= SW_U;
    if (i < SW_2) { emit_w(W2, 64, 64, 136, g_W2_h, g_W2_l, i); return; }
    i -= SW_2;
    if (i < SW_PM) {
        int row = i >> 7, n = i & 127;
        int s = row >> 2, j = row & 3;
        int kp1 = 8 * s + j, kp2 = kp1 + 4;
        uint32_t h1, l1, h2, l2;
        splitpack(cat_msg(Wm, 2 * kp1, n), cat_msg(Wm, 2 * kp1 + 1, n), h1, l1);
        splitpack(cat_msg(Wm, 2 * kp2, n), cat_msg(Wm, 2 * kp2 + 1, n), h2, l2);
        g_Wpm_h[row * 256 + 2 * n] = h1; g_Wpm_h[row * 256 + 2 * n + 1] = h2;
        g_Wpm_l[row * 256 + 2 * n] = l1; g_Wpm_l[row * 256 + 2 * n + 1] = l2;
        return;
    }
    i -= SW_PM;
    if (i < SW_PE) {
        int row = i >> 8, n = i & 255;
        int s = row >> 2, j = row & 3;
        int kp1 = 8 * s + j, kp2 = kp1 + 4;
        uint32_t h1, l1, h2, l2;
        splitpack(cat_eh(W1, 2 * kp1, n), cat_eh(W1, 2 * kp1 + 1, n), h1, l1);
        splitpack(cat_eh(W1, 2 * kp2, n), cat_eh(W1, 2 * kp2 + 1, n), h2, l2);
        g_Wpe_h[row * 512 + 2 * n] = h1; g_Wpe_h[row * 512 + 2 * n + 1] = h2;
        g_Wpe_l[row * 512 + 2 * n] = l1; g_Wpe_l[row * 512 + 2 * n + 1] = l2;
    }
}

// ---------------------------------------------------------------------------
__global__ void enc_kernel(const float* __restrict__ x,
                           const float* __restrict__ W,
                           const float* __restrict__ b) {
    __shared__ float Ws[IND * H];
    __shared__ float bs[H];
    for (int i = threadIdx.x; i < IND * H; i += blockDim.x) Ws[i] = W[i];
    if (threadIdx.x < H) bs[threadIdx.x] = b[threadIdx.x];
    __syncthreads();
    int node = blockIdx.x * blockDim.x + threadIdx.x;
    if (node >= NN) return;
    float xv[IND];
#pragma unroll
    for (int k = 0; k < IND; k++) xv[k] = x[node * IND + k];
#pragma unroll 4
    for (int n = 0; n < H; n += 2) {
        float a0 = bs[n], a1 = bs[n + 1];
#pragma unroll
        for (int k = 0; k < IND; k++) {
            a0 += xv[k] * Ws[k * H + n];
            a1 += xv[k] * Ws[k * H + n + 1];
        }
        g_h[node * H + n] = a0;
        g_h[node * H + n + 1] = a1;
        uint32_t h, l;
        splitpack(a0, a1, h, l);
        int idx = hpack_idx(n >> 1);
        g_hh2[node * 32 + idx] = h;
        g_hl2[node * 32 + idx] = l;
    }
}

// ---------------------------------------------------------------------------
// proj: out[node][blockIdx.y*128 .. +128) = h_packed @ Wcat-block (K=64)
// ---------------------------------------------------------------------------
#define HSTR 20

__global__ void __launch_bounds__(256, 1)
proj_kernel(int which) {
    __shared__ uint2 sh[2 * 64 * HSTR];
    uint2* Ah = sh;
    uint2* Al = sh + 64 * HSTR;
    const uint2* Wh2 = which ? (const uint2*)g_Wpe_h : (const uint2*)g_Wpm_h;
    const uint2* Wl2 = which ? (const uint2*)g_Wpe_l : (const uint2*)g_Wpm_l;
    float* outp = which ? g_P1 : g_PQ;
    const int rs2 = which ? 256 : 128;
    const int ld = rs2;
    const int nbase = blockIdx.x * 64;
    const int colbase = blockIdx.y * 128;
    const int tid = threadIdx.x;
    const int lane = tid & 31, warp = tid >> 5;
    const int g = lane >> 2, tig = lane & 3;
    const int warpM = warp & 3, warpN = warp >> 2;
    const int row0 = warpM * 16 + g;

    uint2 brh[4][8], brl[4][8];
#pragma unroll
    for (int s = 0; s < 4; s++)
#pragma unroll
        for (int nt = 0; nt < 8; nt++) {
            int idx = (s * 4 + tig) * rs2 + colbase + warpN * 64 + nt * 8 + g;
            brh[s][nt] = __ldg(Wh2 + idx);
            brl[s][nt] = __ldg(Wl2 + idx);
        }
    for (int i = tid; i < 64 * 16; i += 256) {
        int nd = i >> 4, u = i & 15;
        int gn = nbase + nd;
        uint2 h = make_uint2(0, 0), l = make_uint2(0, 0);
        if (gn < NN) {
            h = ((const uint2*)g_hh2)[gn * 16 + u];
            l = ((const uint2*)g_hl2)[gn * 16 + u];
        }
        Ah[nd * HSTR + u] = h;
        Al[nd * HSTR + u] = l;
    }
    __syncthreads();

    float acc[8][4] = {};
#pragma unroll
    for (int s = 0; s < 4; s++) {
        uint2 u0h = Ah[ row0      * HSTR + s * 4 + tig];
        uint2 u1h = Ah[(row0 + 8) * HSTR + s * 4 + tig];
        uint2 u0l = Al[ row0      * HSTR + s * 4 + tig];
        uint2 u1l = Al[(row0 + 8) * HSTR + s * 4 + tig];
        uint32_t ah[4] = {u0h.x, u1h.x, u0h.y, u1h.y};
        uint32_t al[4] = {u0l.x, u1l.x, u0l.y, u1l.y};
#pragma unroll
        for (int nt = 0; nt < 8; nt++) {
            mma_bf16(acc[nt], ah, brh[s][nt].x, brh[s][nt].y);
            mma_bf16(acc[nt], al, brh[s][nt].x, brh[s][nt].y);
            mma_bf16(acc[nt], ah, brl[s][nt].x, brl[s][nt].y);
        }
    }
    const int gn0 = nbase + row0, gn1 = gn0 + 8;
#pragma unroll
    for (int nt = 0; nt < 8; nt++) {
        int n = colbase + warpN * 64 + nt * 8 + 2 * tig;
        if (gn0 < NN) *(float2*)(outp + (size_t)gn0 * ld + n) = make_float2(acc[nt][0], acc[nt][1]);
        if (gn1 < NN) *(float2*)(outp + (size_t)gn1 * ld + n) = make_float2(acc[nt][2], acc[nt][3]);
    }
}

// ---------------------------------------------------------------------------
// msg edge pass: agg[dst] += relu(PQ[src,0:64] + PQ[dst,64:128] + ea@Wbot + b)
// Wbot computed inline (8x64 in smem). 4 threads/edge, 16 cols each.
// ---------------------------------------------------------------------------
__global__ void __launch_bounds__(256)
edgepass_kernel(const int* __restrict__ ei, const float* __restrict__ ea,
                const float* __restrict__ Wm, const float* __restrict__ bm) {
    __shared__ float Wb[8 * 64];
    __shared__ float bs[64];
    for (int i = threadIdx.x; i < 512; i += 256) Wb[i] = Wm[(128 + (i >> 6)) * 64 + (i & 63)];
    if (threadIdx.x < 64) bs[threadIdx.x] = bm[threadIdx.x];
    __syncthreads();

    int idx = blockIdx.x * 256 + threadIdx.x;
    int e = idx >> 2, q = idx & 3;
    int s = ei[e], d = ei[EE + e];
    float av[8];
    {
        float4 a0 = *(const float4*)(ea + (size_t)e * 8);
        float4 a1 = *(const float4*)(ea + (size_t)e * 8 + 4);
        av[0] = a0.x; av[1] = a0.y; av[2] = a0.z; av[3] = a0.w;
        av[4] = a1.x; av[5] = a1.y; av[6] = a1.z; av[7] = a1.w;
    }
    const float4* P = (const float4*)(g_PQ + (size_t)s * 128 + q * 16);
    const float4* Q = (const float4*)(g_PQ + (size_t)d * 128 + 64 + q * 16);
    float* o = g_agg + d * 64 + q * 16;
#pragma unroll
    for (int j = 0; j < 4; j++) {
        int c = q * 16 + j * 4;
        float r0 = bs[c], r1 = bs[c + 1], r2 = bs[c + 2], r3 = bs[c + 3];
#pragma unroll
        for (int k = 0; k < 8; k++) {
            float a = av[k];
            r0 += a * Wb[k * 64 + c];
            r1 += a * Wb[k * 64 + c + 1];
            r2 += a * Wb[k * 64 + c + 2];
            r3 += a * Wb[k * 64 + c + 3];
        }
        float4 p = P[j], qq = Q[j];
        float4 v = make_float4(fmaxf(p.x + qq.x + r0, 0.f),
                               fmaxf(p.y + qq.y + r1, 0.f),
                               fmaxf(p.z + qq.z + r2, 0.f),
                               fmaxf(p.w + qq.w + r3, 0.f));
        asm volatile("red.global.add.v4.f32 [%0], {%1,%2,%3,%4};"
                     :: "l"(o + 4 * j), "f"(v.x), "f"(v.y), "f"(v.z), "f"(v.w) : "memory");
    }
}

// ---------------------------------------------------------------------------
// Update: h = relu([h|agg]@Wu + b); zeroes g_agg as it reads it.
// ---------------------------------------------------------------------------
#define ASLOT 36
#define UPD_SMEM (2 * 64 * ASLOT * 8)

__global__ void __launch_bounds__(256, 1)
upd_kernel(const float* __restrict__ bias) {
    extern __shared__ uint2 smU[];
    uint2* Ah = smU;
    uint2* Al = smU + 64 * ASLOT;
    const int nbase = blockIdx.x * 64;
    const int tid = threadIdx.x;
    const int lane = tid & 31, warp = tid >> 5;
    const int g = lane >> 2, tig = lane & 3;
    const int warpM = warp & 3, warpN = warp >> 2;
    const int row0 = warpM * 16 + g;

    uint2 brh[8][4], brl[8][4];
    const uint2* WuH = (const uint2*)g_Wu_h;
    const uint2* WuL = (const uint2*)g_Wu_l;
#pragma unroll
    for (int s = 0; s < 8; s++)
#pragma unroll
        for (int nt = 0; nt < 4; nt++) {
            int idx = (s * 4 + tig) * 68 + warpN * 32 + nt * 8 + g;
            brh[s][nt] = WuH[idx];
            brl[s][nt] = WuL[idx];
        }

    for (int i = tid; i < 64 * 32; i += 256) {
        int nd = i >> 5, u = i & 31;
        int gn = nbase + nd;
        if (u < 16) {
            uint2 h = make_uint2(0, 0), l = make_uint2(0, 0);
            if (gn < NN) {
                h = ((const uint2*)g_hh2)[gn * 16 + u];
                l = ((const uint2*)g_hl2)[gn * 16 + u];
            }
            Ah[nd * ASLOT + u] = h;
            Al[nd * ASLOT + u] = l;
        } else {
            int s = u >> 2, j = u & 3;
            int pa1 = 8 * (s - 4) + j, pa2 = pa1 + 4;
            uint32_t h1 = 0, l1 = 0, h2 = 0, l2 = 0;
            if (gn < NN) {
                float2 v1 = *(float2*)(g_agg + gn * H + 2 * pa1);
                float2 v2 = *(float2*)(g_agg + gn * H + 2 * pa2);
                splitpack(v1.x, v1.y, h1, l1);
                splitpack(v2.x, v2.y, h2, l2);
                *(float2*)(g_agg + gn * H + 2 * pa1) = make_float2(0.f, 0.f);
                *(float2*)(g_agg + gn * H + 2 * pa2) = make_float2(0.f, 0.f);
            }
            Ah[nd * ASLOT + u] = make_uint2(h1, h2);
            Al[nd * ASLOT + u] = make_uint2(l1, l2);
        }
    }
    __syncthreads();

    float acc[4][4] = {};
#pragma unroll
    for (int s = 0; s < 8; s++) {
        uint2 u0h = Ah[ row0      * ASLOT + s * 4 + tig];
        uint2 u1h = Ah[(row0 + 8) * ASLOT + s * 4 + tig];
        uint2 u0l = Al[ row0      * ASLOT + s * 4 + tig];
        uint2 u1l = Al[(row0 + 8) * ASLOT + s * 4 + tig];
        uint32_t ah[4] = {u0h.x, u1h.x, u0h.y, u1h.y};
        uint32_t al[4] = {u0l.x, u1l.x, u0l.y, u1l.y};
#pragma unroll
        for (int nt = 0; nt < 4; nt++) {
            mma_bf16(acc[nt], ah, brh[s][nt].x, brh[s][nt].y);
            mma_bf16(acc[nt], al, brh[s][nt].x, brh[s][nt].y);
            mma_bf16(acc[nt], ah, brl[s][nt].x, brl[s][nt].y);
        }
    }

    const int gn0 = nbase + row0, gn1 = nbase + row0 + 8;
#pragma unroll
    for (int nt = 0; nt < 4; nt++) {
        int n = warpN * 32 + nt * 8 + 2 * tig;
        int p = n >> 1;
        int idx = hpack_idx(p);
        float bb0 = __ldg(bias + n), bb1 = __ldg(bias + n + 1);
        if (gn0 < NN) {
            float v0 = fmaxf(acc[nt][0] + bb0, 0.f);
            float v1 = fmaxf(acc[nt][1] + bb1, 0.f);
            *(float2*)(g_h + gn0 * H + n) = make_float2(v0, v1);
            splitpack(v0, v1, g_hh2[gn0 * 32 + idx], g_hl2[gn0 * 32 + idx]);
        }
        if (gn1 < NN) {
            float v0 = fmaxf(acc[nt][2] + bb0, 0.f);
            float v1 = fmaxf(acc[nt][3] + bb1, 0.f);
            *(float2*)(g_h + gn1 * H + n) = make_float2(v0, v1);
            splitpack(v0, v1, g_hh2[gn1 * 32 + idx], g_hl2[gn1 * 32 + idx]);
        }
    }
}

// ---------------------------------------------------------------------------
// Node head (FFMA)
// ---------------------------------------------------------------------------
__global__ void __launch_bounds__(256)
nodehead_kernel(const float* __restrict__ W1, const float* __restrict__ b1,
                const float* __restrict__ W2, const float* __restrict__ b2,
                float* __restrict__ out) {
    __shared__ float As[64 * 64];
    __shared__ float Ws[64 * 64];
    __shared__ float W2s[64 * 2];
    __shared__ float b2s[2];
    int nbase = blockIdx.x * 64;

    for (int i = threadIdx.x; i < 64 * 64; i += 256) Ws[i] = W1[i];
    if (threadIdx.x < 128) W2s[threadIdx.x] = W2[threadIdx.x];
    if (threadIdx.x < 2) b2s[threadIdx.x] = b2[threadIdx.x];
    for (int i = threadIdx.x; i < 64 * 64; i += 256) {
        int nd = i >> 6, k = i & 63;
        int gn = nbase + nd;
        As[i] = (gn < NN) ? g_h[gn * H + k] : 0.f;
    }
    __syncthreads();

    int tn = threadIdx.x & 15, te = threadIdx.x >> 4;
    float acc[4][4] = {};
    for (int k = 0; k < 64; k += 4) {
        float4 av4[4];
#pragma unroll
        for (int i = 0; i < 4; i++)
            av4[i] = *(const float4*)(As + (te * 4 + i) * 64 + k);
        const float* av = (const float*)av4;
#pragma unroll
        for (int kk = 0; kk < 4; kk++) {
            float4 w = *(const float4*)(Ws + (k + kk) * H + tn * 4);
#pragma unroll
            for (int i = 0; i < 4; i++) {
                float a = av[i * 4 + kk];
                acc[i][0] += a * w.x;
                acc[i][1] += a * w.y;
                acc[i][2] += a * w.z;
                acc[i][3] += a * w.w;
            }
        }
    }
    __syncthreads();

    float4 bvv = *(const float4*)(b1 + tn * 4);
    const float* bvp = (const float*)&bvv;
#pragma unroll
    for (int i = 0; i < 4; i++)
#pragma unroll
        for (int j = 0; j < 4; j++)
            As[(tn * 4 + j) * 64 + te * 4 + i] = fmaxf(acc[i][j] + bvp[j], 0.f);
    __syncthreads();

    if (threadIdx.x < 128) {
        int nd = threadIdx.x & 63, j = threadIdx.x >> 6;
        int gn = nbase + nd;
        if (gn < NN) {
            float s = b2s[j];
#pragma unroll 8
            for (int k = 0; k < 64; k++) s += As[k * 64 + nd] * W2s[k * 2 + j];
            out[gn * 2 + j] = s;
        }
    }
}

// ---------------------------------------------------------------------------
// Edge head v3: persistent, 64-edge tiles, double-buffered staging of
// P1[src]/Q1[dst]/ea[e]; R1 computed inline (W1bot in smem); C1 split-packed
// in place; GEMM2 (W2 regs) + GEMM3.
// Row (floats): [0,128) P, [136,264) Q, [272,280) ea; stride 408.
// ---------------------------------------------------------------------------
#define SROW 408
#define BUFW (64 * SROW)
#define NT_EH (EE / 64)
#define EH_SMEM (2 * BUFW * 4 + (1024 + 128 + 384 + 6) * 4)   // 215064 B

__device__ __forceinline__ void stage_eh(float* Sb,
        const int* __restrict__ src, const int* __restrict__ dst,
        const float* __restrict__ ea, int tbase, int tid) {
    int e = tid >> 2, sub = tid & 3;
    int ge = tbase + e;
    uint32_t rb = (uint32_t)__cvta_generic_to_shared(Sb + e * SROW);
    const float* p;
    uint32_t ofs;
    if (sub == 0)      { p = g_P1 + (size_t)src[ge] * 256;        ofs = 0; }
    else if (sub == 1) { p = g_P1 + (size_t)src[ge] * 256 + 64;   ofs = 256; }
    else if (sub == 2) { p = g_P1 + (size_t)dst[ge] * 256 + 128;  ofs = 544; }
    else               { p = g_P1 + (size_t)dst[ge] * 256 + 192;  ofs = 800; }
#pragma unroll
    for (int j = 0; j < 16; j++) CP_ASYNC16(rb + ofs + j * 16, p + j * 4);
    if (sub == 1) CP_ASYNC16(rb + 1088, ea + (size_t)ge * 8);
    if (sub == 3) CP_ASYNC16(rb + 1104, ea + (size_t)ge * 8 + 4);
}

__global__ void __launch_bounds__(256, 1)
edgehead_kernel(const int* __restrict__ ei, const float* __restrict__ ea,
                const float* __restrict__ W1, const float* __restrict__ b1,
                const float* __restrict__ b2,
                const float* __restrict__ W3, const float* __restrict__ b3,
                float* __restrict__ out) {
    extern __shared__ float smF[];
    float* W1b = smF + 2 * BUFW;      // 1024: W1[128+k][c], k<8, c<128
    float* b1s = W1b + 1024;          // 128
    float* W3s = b1s + 128;           // 384
    float* b3s = W3s + 384;           // 6
    const int* src = ei;
    const int* dst = ei + EE;
    const int tid = threadIdx.x;

    for (int i = tid; i < 1024; i += 256) W1b[i] = W1[(128 + (i >> 7)) * 128 + (i & 127)];
    for (int i = tid; i < 128; i += 256) b1s[i] = b1[i];
    for (int i = tid; i < 384; i += 256) W3s[i] = W3[i];
    if (tid < 6) b3s[tid] = b3[tid];

    const int lane = tid & 31, warp = tid >> 5;
    const int g = lane >> 2, tig = lane & 3;
    const int warpM = warp & 3, warpN = warp >> 2;
    const int row0 = warpM * 16 + g;

    uint2 brh[8][4], brl[8][4];
    const uint2* W2H = (const uint2*)g_W2_h;
    const uint2* W2L = (const uint2*)g_W2_l;
#pragma unroll
    for (int s = 0; s < 8; s++)
#pragma unroll
        for (int nt = 0; nt < 4; nt++) {
            int idx = (s * 4 + tig) * 68 + warpN * 32 + nt * 8 + g;
            brh[s][nt] = W2H[idx];
            brl[s][nt] = W2L[idx];
        }
    float2 b2v[4];
#pragma unroll
    for (int nt = 0; nt < 4; nt++) {
        int n = warpN * 32 + nt * 8 + 2 * tig;
        b2v[nt] = make_float2(__ldg(b2 + n), __ldg(b2 + n + 1));
    }
    __syncthreads();

    int t = blockIdx.x, cur = 0;
    if (t < NT_EH) stage_eh(smF, src, dst, ea, t * 64, tid);
    CP_COMMIT();

    const int e = tid >> 2, q = tid & 3;
    const int off0 = (q == 0) ? 0 : (q == 1) ? 4 : (q == 2) ? 1 : 5;
    const int off1 = off0 + 2;

    for (; t < NT_EH; t += GRID_P) {
        int tn = t + GRID_P;
        if (tn < NT_EH) stage_eh(smF + (cur ^ 1) * BUFW, src, dst, ea, tn * 64, tid);
        CP_COMMIT();
        CP_WAIT1();
        __syncthreads();

        float* Sb = smF + cur * BUFW;
        const int ebase = t * 64;

        // phase 1: C1 = relu(P + Q + ea@W1bot + b1) -> regs, split-packed
        uint32_t c1h[16], c1l[16];
        {
            const float* base = Sb + e * SROW;
            float av[8];
#pragma unroll
            for (int k = 0; k < 8; k++) av[k] = base[272 + k];
#pragma unroll
            for (int j = 0; j < 8; j++) {
                int c = 4 * q + 16 * j;
                float r0 = b1s[c], r1 = b1s[c + 1], r2 = b1s[c + 2], r3 = b1s[c + 3];
#pragma unroll
                for (int k = 0; k < 8; k++) {
                    float a = av[k];
                    r0 += a * W1b[k * 128 + c];
                    r1 += a * W1b[k * 128 + c + 1];
                    r2 += a * W1b[k * 128 + c + 2];
                    r3 += a * W1b[k * 128 + c + 3];
                }
                float4 p  = *(const float4*)(base + c);
                float4 qq = *(const float4*)(base + 136 + c);
                float v0 = fmaxf(p.x + qq.x + r0, 0.f);
                float v1 = fmaxf(p.y + qq.y + r1, 0.f);
                float v2 = fmaxf(p.z + qq.z + r2, 0.f);
                float v3 = fmaxf(p.w + qq.w + r3, 0.f);
                splitpack(v0, v1, c1h[2 * j], c1l[2 * j]);
                splitpack(v2, v3, c1h[2 * j + 1], c1l[2 * j + 1]);
            }
        }
        __syncthreads();

        // phase 2: write C1 planes (u32 stride 72)
        {
            uint32_t* bh = (uint32_t*)Sb + e * 72;
            uint32_t* bl = (uint32_t*)Sb + 64 * 72 + e * 72;
#pragma unroll
            for (int j = 0; j < 8; j++) {
                bh[8 * j + off0] = c1h[2 * j];
                bh[8 * j + off1] = c1h[2 * j + 1];
                bl[8 * j + off0] = c1l[2 * j];
                bl[8 * j + off1] = c1l[2 * j + 1];
            }
        }
        __syncthreads();

        // phase 3: GEMM2 (bf16x3, W2 regs)
        const uint2* Ch2 = (const uint2*)Sb;
        const uint2* Cl2 = Ch2 + 64 * 36;
        float acc2[4][4] = {};
#pragma unroll
        for (int s = 0; s < 8; s++) {
            uint2 u0h = Ch2[ row0      * 36 + s * 4 + tig];
            uint2 u1h = Ch2[(row0 + 8) * 36 + s * 4 + tig];
            uint2 u0l = Cl2[ row0      * 36 + s * 4 + tig];
            uint2 u1l = Cl2[(row0 + 8) * 36 + s * 4 + tig];
            uint32_t ah[4] = {u0h.x, u1h.x, u0h.y, u1h.y};
            uint32_t al[4] = {u0l.x, u1l.x, u0l.y, u1l.y};
#pragma unroll
            for (int nt = 0; nt < 4; nt++) {
                mma_bf16(acc2[nt], ah, brh[s][nt].x, brh[s][nt].y);
                mma_bf16(acc2[nt], al, brh[s][nt].x, brh[s][nt].y);
                mma_bf16(acc2[nt], ah, brl[s][nt].x, brl[s][nt].y);
            }
        }

        // epilogue2: C2 fp32 [64][65] at word 9216 (disjoint from C1 region)
        float* C2 = Sb + 9216;
#pragma unroll
        for (int nt = 0; nt < 4; nt++) {
            int n = warpN * 32 + nt * 8 + 2 * tig;
            C2[ row0      * 65 + n    ] = fmaxf(acc2[nt][0] + b2v[nt].x, 0.f);
            C2[ row0      * 65 + n + 1] = fmaxf(acc2[nt][1] + b2v[nt].y, 0.f);
            C2[(row0 + 8) * 65 + n    ] = fmaxf(acc2[nt][2] + b2v[nt].x, 0.f);
            C2[(row0 + 8) * 65 + n + 1] = fmaxf(acc2[nt][3] + b2v[nt].y, 0.f);
        }
        __syncthreads();

        // GEMM3
        for (int w = tid; w < 384; w += 256) {
            int ee = w & 63, j = w >> 6;
            float s = b3s[j];
#pragma unroll 8
            for (int k = 0; k < 64; k++) s += C2[ee * 65 + k] * W3s[k * 6 + j];
            out[(ebase + ee) * 6 + j] = s;
        }
        __syncthreads();
        cur ^= 1;
    }
}

// ---------------------------------------------------------------------------

extern "C" void kernel_launch(void* const* d_in, const int* in_sizes, int n_in,
                              void* d_out, int out_size) {
    const float* x     = (const float*)d_in[0];
    const int*   ei    = (const int*)d_in[1];
    const float* ea    = (const float*)d_in[2];
    const float* W_enc = (const float*)d_in[3];
    const float* b_enc = (const float*)d_in[4];
    const float* W_msg = (const float*)d_in[5];
    const float* b_msg = (const float*)d_in[6];
    const float* W_upd = (const float*)d_in[7];
    const float* b_upd = (const float*)d_in[8];
    const float* W_nd1 = (const float*)d_in[9];
    const float* b_nd1 = (const float*)d_in[10];
    const float* W_nd2 = (const float*)d_in[11];
    const float* b_nd2 = (const float*)d_in[12];
    const float* W_ed1 = (const float*)d_in[13];
    const float* b_ed1 = (const float*)d_in[14];
    const float* W_ed2 = (const float*)d_in[15];
    const float* b_ed2 = (const float*)d_in[16];
    const float* W_ed3 = (const float*)d_in[17];
    const float* b_ed3 = (const float*)d_in[18];
    float* out = (float*)d_out;

    cudaFuncSetAttribute(upd_kernel, cudaFuncAttributeMaxDynamicSharedMemorySize, UPD_SMEM);
    cudaFuncSetAttribute(edgehead_kernel, cudaFuncAttributeMaxDynamicSharedMemorySize, EH_SMEM);

    split_w_kernel<<<(SW_TOTAL + 255) / 256, 256>>>(W_upd, W_ed2, W_msg, W_ed1);
    enc_kernel<<<(NN + 255) / 256, 256>>>(x, W_enc, b_enc);

    dim3 pgm((NN + 63) / 64, 1);
    proj_kernel<<<pgm, 256>>>(0);
    for (int l = 0; l < 3; l++) {
        edgepass_kernel<<<EE * 4 / 256, 256>>>(ei, ea, W_msg, b_msg);
        upd_kernel<<<(NN + 63) / 64, 256, UPD_SMEM>>>(b_upd);
        if (l < 2) proj_kernel<<<pgm, 256>>>(0);
    }
    nodehead_kernel<<<(NN + 63) / 64, 256>>>(W_nd1, b_nd1, W_nd2, b_nd2, out);
    dim3 pge((NN + 63) / 64, 2);
    proj_kernel<<<pge, 256>>>(1);
    edgehead_kernel<<<GRID_P, 256, EH_SMEM>>>(ei, ea, W_ed1, b_ed1, b_ed2,
                                              W_ed3, b_ed3, out + 2 * NN);
}

// round 15
// speedup vs baseline: 1.2350x; 1.1755x over previous
#include <cuda_runtime.h>
#include <cstdint>

#define NN 50000
#define EE 800000
#define IND 16
#define H 64
#define EAD 8

#define GRID_P 148

__device__ float g_h[NN * H];
__device__ float g_agg[NN * H];        // zero-init; re-zeroed by every upd round
__device__ uint32_t g_hh2[NN * 32];
__device__ uint32_t g_hl2[NN * 32];
__device__ float g_PQ[NN * 128];
__device__ float g_P1[NN * 256];

__device__ uint32_t g_Wu_h[32 * 136],  g_Wu_l[32 * 136];
__device__ uint32_t g_W2_h[32 * 136],  g_W2_l[32 * 136];
__device__ uint32_t g_Wpm_h[16 * 256], g_Wpm_l[16 * 256];
__device__ uint32_t g_Wpe_h[16 * 512], g_Wpe_l[16 * 512];

// ---------------------------------------------------------------------------
__device__ __forceinline__ void splitpack(float a0, float a1, uint32_t& hi, uint32_t& lo) {
    uint32_t h, l;
    asm("cvt.rn.bf16x2.f32 %0, %1, %2;" : "=r"(h) : "f"(a1), "f"(a0));
    float r0 = a0 - __uint_as_float(h << 16);
    float r1 = a1 - __uint_as_float(h & 0xFFFF0000u);
    asm("cvt.rn.bf16x2.f32 %0, %1, %2;" : "=r"(l) : "f"(r1), "f"(r0));
    hi = h; lo = l;
}

__device__ __forceinline__ void mma_bf16(float* c, const uint32_t* a, uint32_t b0, uint32_t b1) {
    asm volatile(
        "mma.sync.aligned.m16n8k16.row.col.f32.bf16.bf16.f32 "
        "{%0,%1,%2,%3}, {%4,%5,%6,%7}, {%8,%9}, {%0,%1,%2,%3};"
        : "+f"(c[0]), "+f"(c[1]), "+f"(c[2]), "+f"(c[3])
        : "r"(a[0]), "r"(a[1]), "r"(a[2]), "r"(a[3]), "r"(b0), "r"(b1));
}

#define CP_ASYNC16(saddr, gptr) \
    asm volatile("cp.async.cg.shared.global [%0], [%1], 16;" :: "r"(saddr), "l"(gptr) : "memory")
#define CP_COMMIT() asm volatile("cp.async.commit_group;" ::: "memory")
#define CP_WAIT1()  asm volatile("cp.async.wait_group 1;" ::: "memory")

__device__ __forceinline__ int hpack_idx(int p) {
    int s = p >> 3, r = p & 7;
    return (r < 4) ? (s * 4 + r) * 2 : (s * 4 + r - 4) * 2 + 1;
}

// ---------------------------------------------------------------------------
__device__ __forceinline__ void emit_w(const float* W, int Kp, int N, int RS,
                                       uint32_t* oh, uint32_t* ol, int i) {
    int row = i / N, n = i - row * N;
    int s = row >> 2, j = row & 3;
    int kp1 = 8 * s + j, kp2 = kp1 + 4;
    float a0 = 0.f, a1 = 0.f, c0 = 0.f, c1 = 0.f;
    if (kp1 < Kp) { a0 = W[(2 * kp1) * N + n]; a1 = W[(2 * kp1 + 1) * N + n]; }
    if (kp2 < Kp) { c0 = W[(2 * kp2) * N + n]; c1 = W[(2 * kp2 + 1) * N + n]; }
    uint32_t h1, l1, h2, l2;
    splitpack(a0, a1, h1, l1);
    splitpack(c0, c1, h2, l2);
    oh[row * RS + 2 * n] = h1; oh[row * RS + 2 * n + 1] = h2;
    ol[row * RS + 2 * n] = l1; ol[row * RS + 2 * n + 1] = l2;
}

__device__ __forceinline__ float cat_msg(const float* Wm, int k, int n) {
    return (n < 64) ? Wm[k * 64 + n] : Wm[(64 + k) * 64 + (n - 64)];
}
__device__ __forceinline__ float cat_eh(const float* W1, int k, int n) {
    return (n < 128) ? W1[k * 128 + n] : W1[(64 + k) * 128 + (n - 128)];
}

#define SW_U  (32*64)
#define SW_2  (32*64)
#define SW_PM (16*128)
#define SW_PE (16*256)
#define SW_TOTAL (SW_U + SW_2 + SW_PM + SW_PE)

__global__ void split_w_kernel(const float* __restrict__ Wu, const float* __restrict__ W2,
                               const float* __restrict__ Wm, const float* __restrict__ W1) {
    int i = blockIdx.x * 256 + threadIdx.x;
    if (i < SW_U) { emit_w(Wu, 64, 64, 136, g_Wu_h, g_Wu_l, i); return; }
    i -= SW_U;
    if (i < SW_2) { emit_w(W2, 64, 64, 136, g_W2_h, g_W2_l, i); return; }
    i -= SW_2;
    if (i < SW_PM) {
        int row = i >> 7, n = i & 127;
        int s = row >> 2, j = row & 3;
        int kp1 = 8 * s + j, kp2 = kp1 + 4;
        uint32_t h1, l1, h2, l2;
        splitpack(cat_msg(Wm, 2 * kp1, n), cat_msg(Wm, 2 * kp1 + 1, n), h1, l1);
        splitpack(cat_msg(Wm, 2 * kp2, n), cat_msg(Wm, 2 * kp2 + 1, n), h2, l2);
        g_Wpm_h[row * 256 + 2 * n] = h1; g_Wpm_h[row * 256 + 2 * n + 1] = h2;
        g_Wpm_l[row * 256 + 2 * n] = l1; g_Wpm_l[row * 256 + 2 * n + 1] = l2;
        return;
    }
    i -= SW_PM;
    if (i < SW_PE) {
        int row = i >> 8, n = i & 255;
        int s = row >> 2, j = row & 3;
        int kp1 = 8 * s + j, kp2 = kp1 + 4;
        uint32_t h1, l1, h2, l2;
        splitpack(cat_eh(W1, 2 * kp1, n), cat_eh(W1, 2 * kp1 + 1, n), h1, l1);
        splitpack(cat_eh(W1, 2 * kp2, n), cat_eh(W1, 2 * kp2 + 1, n), h2, l2);
        g_Wpe_h[row * 512 + 2 * n] = h1; g_Wpe_h[row * 512 + 2 * n + 1] = h2;
        g_Wpe_l[row * 512 + 2 * n] = l1; g_Wpe_l[row * 512 + 2 * n + 1] = l2;
    }
}

// ---------------------------------------------------------------------------
__global__ void enc_kernel(const float* __restrict__ x,
                           const float* __restrict__ W,
                           const float* __restrict__ b) {
    __shared__ float Ws[IND * H];
    __shared__ float bs[H];
    for (int i = threadIdx.x; i < IND * H; i += blockDim.x) Ws[i] = W[i];
    if (threadIdx.x < H) bs[threadIdx.x] = b[threadIdx.x];
    __syncthreads();
    int node = blockIdx.x * blockDim.x + threadIdx.x;
    if (node >= NN) return;
    float xv[IND];
#pragma unroll
    for (int k = 0; k < IND; k++) xv[k] = x[node * IND + k];
#pragma unroll 4
    for (int n = 0; n < H; n += 2) {
        float a0 = bs[n], a1 = bs[n + 1];
#pragma unroll
        for (int k = 0; k < IND; k++) {
            a0 += xv[k] * Ws[k * H + n];
            a1 += xv[k] * Ws[k * H + n + 1];
        }
        g_h[node * H + n] = a0;
        g_h[node * H + n + 1] = a1;
        uint32_t h, l;
        splitpack(a0, a1, h, l);
        int idx = hpack_idx(n >> 1);
        g_hh2[node * 32 + idx] = h;
        g_hl2[node * 32 + idx] = l;
    }
}

// ---------------------------------------------------------------------------
// proj: out[node][blockIdx.y*128 .. +128) = h_packed @ Wcat-block (K=64)
// ---------------------------------------------------------------------------
#define HSTR 20

__global__ void __launch_bounds__(256, 1)
proj_kernel(int which) {
    __shared__ uint2 sh[2 * 64 * HSTR];
    uint2* Ah = sh;
    uint2* Al = sh + 64 * HSTR;
    const uint2* Wh2 = which ? (const uint2*)g_Wpe_h : (const uint2*)g_Wpm_h;
    const uint2* Wl2 = which ? (const uint2*)g_Wpe_l : (const uint2*)g_Wpm_l;
    float* outp = which ? g_P1 : g_PQ;
    const int rs2 = which ? 256 : 128;
    const int ld = rs2;
    const int nbase = blockIdx.x * 64;
    const int colbase = blockIdx.y * 128;
    const int tid = threadIdx.x;
    const int lane = tid & 31, warp = tid >> 5;
    const int g = lane >> 2, tig = lane & 3;
    const int warpM = warp & 3, warpN = warp >> 2;
    const int row0 = warpM * 16 + g;

    uint2 brh[4][8], brl[4][8];
#pragma unroll
    for (int s = 0; s < 4; s++)
#pragma unroll
        for (int nt = 0; nt < 8; nt++) {
            int idx = (s * 4 + tig) * rs2 + colbase + warpN * 64 + nt * 8 + g;
            brh[s][nt] = __ldg(Wh2 + idx);
            brl[s][nt] = __ldg(Wl2 + idx);
        }
    for (int i = tid; i < 64 * 16; i += 256) {
        int nd = i >> 4, u = i & 15;
        int gn = nbase + nd;
        uint2 h = make_uint2(0, 0), l = make_uint2(0, 0);
        if (gn < NN) {
            h = ((const uint2*)g_hh2)[gn * 16 + u];
            l = ((const uint2*)g_hl2)[gn * 16 + u];
        }
        Ah[nd * HSTR + u] = h;
        Al[nd * HSTR + u] = l;
    }
    __syncthreads();

    float acc[8][4] = {};
#pragma unroll
    for (int s = 0; s < 4; s++) {
        uint2 u0h = Ah[ row0      * HSTR + s * 4 + tig];
        uint2 u1h = Ah[(row0 + 8) * HSTR + s * 4 + tig];
        uint2 u0l = Al[ row0      * HSTR + s * 4 + tig];
        uint2 u1l = Al[(row0 + 8) * HSTR + s * 4 + tig];
        uint32_t ah[4] = {u0h.x, u1h.x, u0h.y, u1h.y};
        uint32_t al[4] = {u0l.x, u1l.x, u0l.y, u1l.y};
#pragma unroll
        for (int nt = 0; nt < 8; nt++) {
            mma_bf16(acc[nt], ah, brh[s][nt].x, brh[s][nt].y);
            mma_bf16(acc[nt], al, brh[s][nt].x, brh[s][nt].y);
            mma_bf16(acc[nt], ah, brl[s][nt].x, brl[s][nt].y);
        }
    }
    const int gn0 = nbase + row0, gn1 = gn0 + 8;
#pragma unroll
    for (int nt = 0; nt < 8; nt++) {
        int n = colbase + warpN * 64 + nt * 8 + 2 * tig;
        if (gn0 < NN) *(float2*)(outp + (size_t)gn0 * ld + n) = make_float2(acc[nt][0], acc[nt][1]);
        if (gn1 < NN) *(float2*)(outp + (size_t)gn1 * ld + n) = make_float2(acc[nt][2], acc[nt][3]);
    }
}

// ---------------------------------------------------------------------------
// msg edge pass: agg[dst] += relu(PQ[src,0:64] + PQ[dst,64:128] + ea@Wbot + b)
// Wbot inline (8x64 smem). 4 threads/edge; COALESCED: c = j*16 + q*4 so the
// 4 lanes of an edge cover one contiguous 64B chunk per iteration (loads+red).
// ---------------------------------------------------------------------------
__global__ void __launch_bounds__(256)
edgepass_kernel(const int* __restrict__ ei, const float* __restrict__ ea,
                const float* __restrict__ Wm, const float* __restrict__ bm) {
    __shared__ float Wb[8 * 64];
    __shared__ float bs[64];
    for (int i = threadIdx.x; i < 512; i += 256) Wb[i] = Wm[(128 + (i >> 6)) * 64 + (i & 63)];
    if (threadIdx.x < 64) bs[threadIdx.x] = bm[threadIdx.x];
    __syncthreads();

    int idx = blockIdx.x * 256 + threadIdx.x;
    int e = idx >> 2, q = idx & 3;
    int s = ei[e], d = ei[EE + e];
    float av[8];
    {
        float4 a0 = *(const float4*)(ea + (size_t)e * 8);
        float4 a1 = *(const float4*)(ea + (size_t)e * 8 + 4);
        av[0] = a0.x; av[1] = a0.y; av[2] = a0.z; av[3] = a0.w;
        av[4] = a1.x; av[5] = a1.y; av[6] = a1.z; av[7] = a1.w;
    }
    const float* Pb = g_PQ + (size_t)s * 128;
    const float* Qb = g_PQ + (size_t)d * 128 + 64;
    float* ob = g_agg + d * 64;
#pragma unroll
    for (int j = 0; j < 4; j++) {
        int c = j * 16 + q * 4;
        float r0 = bs[c], r1 = bs[c + 1], r2 = bs[c + 2], r3 = bs[c + 3];
#pragma unroll
        for (int k = 0; k < 8; k++) {
            float a = av[k];
            r0 += a * Wb[k * 64 + c];
            r1 += a * Wb[k * 64 + c + 1];
            r2 += a * Wb[k * 64 + c + 2];
            r3 += a * Wb[k * 64 + c + 3];
        }
        float4 p  = *(const float4*)(Pb + c);
        float4 qq = *(const float4*)(Qb + c);
        float4 v = make_float4(fmaxf(p.x + qq.x + r0, 0.f),
                               fmaxf(p.y + qq.y + r1, 0.f),
                               fmaxf(p.z + qq.z + r2, 0.f),
                               fmaxf(p.w + qq.w + r3, 0.f));
        asm volatile("red.global.add.v4.f32 [%0], {%1,%2,%3,%4};"
                     :: "l"(ob + c), "f"(v.x), "f"(v.y), "f"(v.z), "f"(v.w) : "memory");
    }
}

// ---------------------------------------------------------------------------
// Update: h = relu([h|agg]@Wu + b); zeroes g_agg as it reads it.
// ---------------------------------------------------------------------------
#define ASLOT 36
#define UPD_SMEM (2 * 64 * ASLOT * 8)

__global__ void __launch_bounds__(256, 1)
upd_kernel(const float* __restrict__ bias) {
    extern __shared__ uint2 smU[];
    uint2* Ah = smU;
    uint2* Al = smU + 64 * ASLOT;
    const int nbase = blockIdx.x * 64;
    const int tid = threadIdx.x;
    const int lane = tid & 31, warp = tid >> 5;
    const int g = lane >> 2, tig = lane & 3;
    const int warpM = warp & 3, warpN = warp >> 2;
    const int row0 = warpM * 16 + g;

    uint2 brh[8][4], brl[8][4];
    const uint2* WuH = (const uint2*)g_Wu_h;
    const uint2* WuL = (const uint2*)g_Wu_l;
#pragma unroll
    for (int s = 0; s < 8; s++)
#pragma unroll
        for (int nt = 0; nt < 4; nt++) {
            int idx = (s * 4 + tig) * 68 + warpN * 32 + nt * 8 + g;
            brh[s][nt] = WuH[idx];
            brl[s][nt] = WuL[idx];
        }

    for (int i = tid; i < 64 * 32; i += 256) {
        int nd = i >> 5, u = i & 31;
        int gn = nbase + nd;
        if (u < 16) {
            uint2 h = make_uint2(0, 0), l = make_uint2(0, 0);
            if (gn < NN) {
                h = ((const uint2*)g_hh2)[gn * 16 + u];
                l = ((const uint2*)g_hl2)[gn * 16 + u];
            }
            Ah[nd * ASLOT + u] = h;
            Al[nd * ASLOT + u] = l;
        } else {
            int s = u >> 2, j = u & 3;
            int pa1 = 8 * (s - 4) + j, pa2 = pa1 + 4;
            uint32_t h1 = 0, l1 = 0, h2 = 0, l2 = 0;
            if (gn < NN) {
                float2 v1 = *(float2*)(g_agg + gn * H + 2 * pa1);
                float2 v2 = *(float2*)(g_agg + gn * H + 2 * pa2);
                splitpack(v1.x, v1.y, h1, l1);
                splitpack(v2.x, v2.y, h2, l2);
                *(float2*)(g_agg + gn * H + 2 * pa1) = make_float2(0.f, 0.f);
                *(float2*)(g_agg + gn * H + 2 * pa2) = make_float2(0.f, 0.f);
            }
            Ah[nd * ASLOT + u] = make_uint2(h1, h2);
            Al[nd * ASLOT + u] = make_uint2(l1, l2);
        }
    }
    __syncthreads();

    float acc[4][4] = {};
#pragma unroll
    for (int s = 0; s < 8; s++) {
        uint2 u0h = Ah[ row0      * ASLOT + s * 4 + tig];
        uint2 u1h = Ah[(row0 + 8) * ASLOT + s * 4 + tig];
        uint2 u0l = Al[ row0      * ASLOT + s * 4 + tig];
        uint2 u1l = Al[(row0 + 8) * ASLOT + s * 4 + tig];
        uint32_t ah[4] = {u0h.x, u1h.x, u0h.y, u1h.y};
        uint32_t al[4] = {u0l.x, u1l.x, u0l.y, u1l.y};
#pragma unroll
        for (int nt = 0; nt < 4; nt++) {
            mma_bf16(acc[nt], ah, brh[s][nt].x, brh[s][nt].y);
            mma_bf16(acc[nt], al, brh[s][nt].x, brh[s][nt].y);
            mma_bf16(acc[nt], ah, brl[s][nt].x, brl[s][nt].y);
        }
    }

    const int gn0 = nbase + row0, gn1 = nbase + row0 + 8;
#pragma unroll
    for (int nt = 0; nt < 4; nt++) {
        int n = warpN * 32 + nt * 8 + 2 * tig;
        int p = n >> 1;
        int idx = hpack_idx(p);
        float bb0 = __ldg(bias + n), bb1 = __ldg(bias + n + 1);
        if (gn0 < NN) {
            float v0 = fmaxf(acc[nt][0] + bb0, 0.f);
            float v1 = fmaxf(acc[nt][1] + bb1, 0.f);
            *(float2*)(g_h + gn0 * H + n) = make_float2(v0, v1);
            splitpack(v0, v1, g_hh2[gn0 * 32 + idx], g_hl2[gn0 * 32 + idx]);
        }
        if (gn1 < NN) {
            float v0 = fmaxf(acc[nt][2] + bb0, 0.f);
            float v1 = fmaxf(acc[nt][3] + bb1, 0.f);
            *(float2*)(g_h + gn1 * H + n) = make_float2(v0, v1);
            splitpack(v0, v1, g_hh2[gn1 * 32 + idx], g_hl2[gn1 * 32 + idx]);
        }
    }
}

// ---------------------------------------------------------------------------
// Node head (FFMA)
// ---------------------------------------------------------------------------
__global__ void __launch_bounds__(256)
nodehead_kernel(const float* __restrict__ W1, const float* __restrict__ b1,
                const float* __restrict__ W2, const float* __restrict__ b2,
                float* __restrict__ out) {
    __shared__ float As[64 * 64];
    __shared__ float Ws[64 * 64];
    __shared__ float W2s[64 * 2];
    __shared__ float b2s[2];
    int nbase = blockIdx.x * 64;

    for (int i = threadIdx.x; i < 64 * 64; i += 256) Ws[i] = W1[i];
    if (threadIdx.x < 128) W2s[threadIdx.x] = W2[threadIdx.x];
    if (threadIdx.x < 2) b2s[threadIdx.x] = b2[threadIdx.x];
    for (int i = threadIdx.x; i < 64 * 64; i += 256) {
        int nd = i >> 6, k = i & 63;
        int gn = nbase + nd;
        As[i] = (gn < NN) ? g_h[gn * H + k] : 0.f;
    }
    __syncthreads();

    int tn = threadIdx.x & 15, te = threadIdx.x >> 4;
    float acc[4][4] = {};
    for (int k = 0; k < 64; k += 4) {
        float4 av4[4];
#pragma unroll
        for (int i = 0; i < 4; i++)
            av4[i] = *(const float4*)(As + (te * 4 + i) * 64 + k);
        const float* av = (const float*)av4;
#pragma unroll
        for (int kk = 0; kk < 4; kk++) {
            float4 w = *(const float4*)(Ws + (k + kk) * H + tn * 4);
#pragma unroll
            for (int i = 0; i < 4; i++) {
                float a = av[i * 4 + kk];
                acc[i][0] += a * w.x;
                acc[i][1] += a * w.y;
                acc[i][2] += a * w.z;
                acc[i][3] += a * w.w;
            }
        }
    }
    __syncthreads();

    float4 bvv = *(const float4*)(b1 + tn * 4);
    const float* bvp = (const float*)&bvv;
#pragma unroll
    for (int i = 0; i < 4; i++)
#pragma unroll
        for (int j = 0; j < 4; j++)
            As[(tn * 4 + j) * 64 + te * 4 + i] = fmaxf(acc[i][j] + bvp[j], 0.f);
    __syncthreads();

    if (threadIdx.x < 128) {
        int nd = threadIdx.x & 63, j = threadIdx.x >> 6;
        int gn = nbase + nd;
        if (gn < NN) {
            float s = b2s[j];
#pragma unroll 8
            for (int k = 0; k < 64; k++) s += As[k * 64 + nd] * W2s[k * 2 + j];
            out[gn * 2 + j] = s;
        }
    }
}

// ---------------------------------------------------------------------------
// Edge head v3: persistent, 64-edge tiles, double-buffered staging of
// P1[src]/Q1[dst]/ea[e]; R1 computed inline (W1bot in smem); C1 split-packed
// in place; GEMM2 (W2 regs) + GEMM3.
// Row (floats): [0,128) P, [136,264) Q, [272,280) ea; stride 408.
// ---------------------------------------------------------------------------
#define SROW 408
#define BUFW (64 * SROW)
#define NT_EH (EE / 64)
#define EH_SMEM (2 * BUFW * 4 + (1024 + 128 + 384 + 6) * 4)   // 215064 B

__device__ __forceinline__ void stage_eh(float* Sb,
        const int* __restrict__ src, const int* __restrict__ dst,
        const float* __restrict__ ea, int tbase, int tid) {
    int e = tid >> 2, sub = tid & 3;
    int ge = tbase + e;
    uint32_t rb = (uint32_t)__cvta_generic_to_shared(Sb + e * SROW);
    const float* p;
    uint32_t ofs;
    if (sub == 0)      { p = g_P1 + (size_t)src[ge] * 256;        ofs = 0; }
    else if (sub == 1) { p = g_P1 + (size_t)src[ge] * 256 + 64;   ofs = 256; }
    else if (sub == 2) { p = g_P1 + (size_t)dst[ge] * 256 + 128;  ofs = 544; }
    else               { p = g_P1 + (size_t)dst[ge] * 256 + 192;  ofs = 800; }
#pragma unroll
    for (int j = 0; j < 16; j++) CP_ASYNC16(rb + ofs + j * 16, p + j * 4);
    if (sub == 1) CP_ASYNC16(rb + 1088, ea + (size_t)ge * 8);
    if (sub == 3) CP_ASYNC16(rb + 1104, ea + (size_t)ge * 8 + 4);
}

__global__ void __launch_bounds__(256, 1)
edgehead_kernel(const int* __restrict__ ei, const float* __restrict__ ea,
                const float* __restrict__ W1, const float* __restrict__ b1,
                const float* __restrict__ b2,
                const float* __restrict__ W3, const float* __restrict__ b3,
                float* __restrict__ out) {
    extern __shared__ float smF[];
    float* W1b = smF + 2 * BUFW;      // 1024: W1[128+k][c], k<8, c<128
    float* b1s = W1b + 1024;          // 128
    float* W3s = b1s + 128;           // 384
    float* b3s = W3s + 384;           // 6
    const int* src = ei;
    const int* dst = ei + EE;
    const int tid = threadIdx.x;

    for (int i = tid; i < 1024; i += 256) W1b[i] = W1[(128 + (i >> 7)) * 128 + (i & 127)];
    for (int i = tid; i < 128; i += 256) b1s[i] = b1[i];
    for (int i = tid; i < 384; i += 256) W3s[i] = W3[i];
    if (tid < 6) b3s[tid] = b3[tid];

    const int lane = tid & 31, warp = tid >> 5;
    const int g = lane >> 2, tig = lane & 3;
    const int warpM = warp & 3, warpN = warp >> 2;
    const int row0 = warpM * 16 + g;

    uint2 brh[8][4], brl[8][4];
    const uint2* W2H = (const uint2*)g_W2_h;
    const uint2* W2L = (const uint2*)g_W2_l;
#pragma unroll
    for (int s = 0; s < 8; s++)
#pragma unroll
        for (int nt = 0; nt < 4; nt++) {
            int idx = (s * 4 + tig) * 68 + warpN * 32 + nt * 8 + g;
            brh[s][nt] = W2H[idx];
            brl[s][nt] = W2L[idx];
        }
    float2 b2v[4];
#pragma unroll
    for (int nt = 0; nt < 4; nt++) {
        int n = warpN * 32 + nt * 8 + 2 * tig;
        b2v[nt] = make_float2(__ldg(b2 + n), __ldg(b2 + n + 1));
    }
    __syncthreads();

    int t = blockIdx.x, cur = 0;
    if (t < NT_EH) stage_eh(smF, src, dst, ea, t * 64, tid);
    CP_COMMIT();

    const int e = tid >> 2, q = tid & 3;
    const int off0 = (q == 0) ? 0 : (q == 1) ? 4 : (q == 2) ? 1 : 5;
    const int off1 = off0 + 2;

    for (; t < NT_EH; t += GRID_P) {
        int tn = t + GRID_P;
        if (tn < NT_EH) stage_eh(smF + (cur ^ 1) * BUFW, src, dst, ea, tn * 64, tid);
        CP_COMMIT();
        CP_WAIT1();
        __syncthreads();

        float* Sb = smF + cur * BUFW;
        const int ebase = t * 64;

        // phase 1: C1 = relu(P + Q + ea@W1bot + b1) -> regs, split-packed
        uint32_t c1h[16], c1l[16];
        {
            const float* base = Sb + e * SROW;
            float av[8];
#pragma unroll
            for (int k = 0; k < 8; k++) av[k] = base[272 + k];
#pragma unroll
            for (int j = 0; j < 8; j++) {
                int c = 4 * q + 16 * j;
                float r0 = b1s[c], r1 = b1s[c + 1], r2 = b1s[c + 2], r3 = b1s[c + 3];
#pragma unroll
                for (int k = 0; k < 8; k++) {
                    float a = av[k];
                    r0 += a * W1b[k * 128 + c];
                    r1 += a * W1b[k * 128 + c + 1];
                    r2 += a * W1b[k * 128 + c + 2];
                    r3 += a * W1b[k * 128 + c + 3];
                }
                float4 p  = *(const float4*)(base + c);
                float4 qq = *(const float4*)(base + 136 + c);
                float v0 = fmaxf(p.x + qq.x + r0, 0.f);
                float v1 = fmaxf(p.y + qq.y + r1, 0.f);
                float v2 = fmaxf(p.z + qq.z + r2, 0.f);
                float v3 = fmaxf(p.w + qq.w + r3, 0.f);
                splitpack(v0, v1, c1h[2 * j], c1l[2 * j]);
                splitpack(v2, v3, c1h[2 * j + 1], c1l[2 * j + 1]);
            }
        }
        __syncthreads();

        // phase 2: write C1 planes (u32 stride 72)
        {
            uint32_t* bh = (uint32_t*)Sb + e * 72;
            uint32_t* bl = (uint32_t*)Sb + 64 * 72 + e * 72;
#pragma unroll
            for (int j = 0; j < 8; j++) {
                bh[8 * j + off0] = c1h[2 * j];
                bh[8 * j + off1] = c1h[2 * j + 1];
                bl[8 * j + off0] = c1l[2 * j];
                bl[8 * j + off1] = c1l[2 * j + 1];
            }
        }
        __syncthreads();

        // phase 3: GEMM2 (bf16x3, W2 regs)
        const uint2* Ch2 = (const uint2*)Sb;
        const uint2* Cl2 = Ch2 + 64 * 36;
        float acc2[4][4] = {};
#pragma unroll
        for (int s = 0; s < 8; s++) {
            uint2 u0h = Ch2[ row0      * 36 + s * 4 + tig];
            uint2 u1h = Ch2[(row0 + 8) * 36 + s * 4 + tig];
            uint2 u0l = Cl2[ row0      * 36 + s * 4 + tig];
            uint2 u1l = Cl2[(row0 + 8) * 36 + s * 4 + tig];
            uint32_t ah[4] = {u0h.x, u1h.x, u0h.y, u1h.y};
            uint32_t al[4] = {u0l.x, u1l.x, u0l.y, u1l.y};
#pragma unroll
            for (int nt = 0; nt < 4; nt++) {
                mma_bf16(acc2[nt], ah, brh[s][nt].x, brh[s][nt].y);
                mma_bf16(acc2[nt], al, brh[s][nt].x, brh[s][nt].y);
                mma_bf16(acc2[nt], ah, brl[s][nt].x, brl[s][nt].y);
            }
        }

        // epilogue2: C2 fp32 [64][65] at word 9216 (disjoint from C1 region)
        float* C2 = Sb + 9216;
#pragma unroll
        for (int nt = 0; nt < 4; nt++) {
            int n = warpN * 32 + nt * 8 + 2 * tig;
            C2[ row0      * 65 + n    ] = fmaxf(acc2[nt][0] + b2v[nt].x, 0.f);
            C2[ row0      * 65 + n + 1] = fmaxf(acc2[nt][1] + b2v[nt].y, 0.f);
            C2[(row0 + 8) * 65 + n    ] = fmaxf(acc2[nt][2] + b2v[nt].x, 0.f);
            C2[(row0 + 8) * 65 + n + 1] = fmaxf(acc2[nt][3] + b2v[nt].y, 0.f);
        }
        __syncthreads();

        // GEMM3
        for (int w = tid; w < 384; w += 256) {
            int ee = w & 63, j = w >> 6;
            float s = b3s[j];
#pragma unroll 8
            for (int k = 0; k < 64; k++) s += C2[ee * 65 + k] * W3s[k * 6 + j];
            out[(ebase + ee) * 6 + j] = s;
        }
        __syncthreads();
        cur ^= 1;
    }
}

// ---------------------------------------------------------------------------

extern "C" void kernel_launch(void* const* d_in, const int* in_sizes, int n_in,
                              void* d_out, int out_size) {
    const float* x     = (const float*)d_in[0];
    const int*   ei    = (const int*)d_in[1];
    const float* ea    = (const float*)d_in[2];
    const float* W_enc = (const float*)d_in[3];
    const float* b_enc = (const float*)d_in[4];
    const float* W_msg = (const float*)d_in[5];
    const float* b_msg = (const float*)d_in[6];
    const float* W_upd = (const float*)d_in[7];
    const float* b_upd = (const float*)d_in[8];
    const float* W_nd1 = (const float*)d_in[9];
    const float* b_nd1 = (const float*)d_in[10];
    const float* W_nd2 = (const float*)d_in[11];
    const float* b_nd2 = (const float*)d_in[12];
    const float* W_ed1 = (const float*)d_in[13];
    const float* b_ed1 = (const float*)d_in[14];
    const float* W_ed2 = (const float*)d_in[15];
    const float* b_ed2 = (const float*)d_in[16];
    const float* W_ed3 = (const float*)d_in[17];
    const float* b_ed3 = (const float*)d_in[18];
    float* out = (float*)d_out;

    cudaFuncSetAttribute(upd_kernel, cudaFuncAttributeMaxDynamicSharedMemorySize, UPD_SMEM);
    cudaFuncSetAttribute(edgehead_kernel, cudaFuncAttributeMaxDynamicSharedMemorySize, EH_SMEM);

    split_w_kernel<<<(SW_TOTAL + 255) / 256, 256>>>(W_upd, W_ed2, W_msg, W_ed1);
    enc_kernel<<<(NN + 255) / 256, 256>>>(x, W_enc, b_enc);

    dim3 pgm((NN + 63) / 64, 1);
    proj_kernel<<<pgm, 256>>>(0);
    for (int l = 0; l < 3; l++) {
        edgepass_kernel<<<EE * 4 / 256, 256>>>(ei, ea, W_msg, b_msg);
        upd_kernel<<<(NN + 63) / 64, 256, UPD_SMEM>>>(b_upd);
        if (l < 2) proj_kernel<<<pgm, 256>>>(0);
    }
    nodehead_kernel<<<(NN + 63) / 64, 256>>>(W_nd1, b_nd1, W_nd2, b_nd2, out);
    dim3 pge((NN + 63) / 64, 2);
    proj_kernel<<<pge, 256>>>(1);
    edgehead_kernel<<<GRID_P, 256, EH_SMEM>>>(ei, ea, W_ed1, b_ed1, b_ed2,
                                              W_ed3, b_ed3, out + 2 * NN);
}

// round 16
// speedup vs baseline: 1.5038x; 1.2177x over previous
#include <cuda_runtime.h>
#include <cstdint>

#define NN 50000
#define EE 800000
#define IND 16
#define H 64
#define EAD 8

#define GRID_P 148

__device__ float g_h[NN * H];
__device__ float g_agg[NN * H];        // zero-init; re-zeroed by every upd round
__device__ uint32_t g_hh2[NN * 32];
__device__ uint32_t g_hl2[NN * 32];
__device__ float g_PQ[NN * 128];
__device__ float g_P1[NN * 256];

__device__ uint32_t g_Wu_h[32 * 136],  g_Wu_l[32 * 136];
__device__ uint32_t g_W2_h[32 * 136],  g_W2_l[32 * 136];
__device__ uint32_t g_Wpm_h[16 * 256], g_Wpm_l[16 * 256];
__device__ uint32_t g_Wpe_h[16 * 512], g_Wpe_l[16 * 512];

// ---------------------------------------------------------------------------
__device__ __forceinline__ void splitpack(float a0, float a1, uint32_t& hi, uint32_t& lo) {
    uint32_t h, l;
    asm("cvt.rn.bf16x2.f32 %0, %1, %2;" : "=r"(h) : "f"(a1), "f"(a0));
    float r0 = a0 - __uint_as_float(h << 16);
    float r1 = a1 - __uint_as_float(h & 0xFFFF0000u);
    asm("cvt.rn.bf16x2.f32 %0, %1, %2;" : "=r"(l) : "f"(r1), "f"(r0));
    hi = h; lo = l;
}

__device__ __forceinline__ void mma_bf16(float* c, const uint32_t* a, uint32_t b0, uint32_t b1) {
    asm volatile(
        "mma.sync.aligned.m16n8k16.row.col.f32.bf16.bf16.f32 "
        "{%0,%1,%2,%3}, {%4,%5,%6,%7}, {%8,%9}, {%0,%1,%2,%3};"
        : "+f"(c[0]), "+f"(c[1]), "+f"(c[2]), "+f"(c[3])
        : "r"(a[0]), "r"(a[1]), "r"(a[2]), "r"(a[3]), "r"(b0), "r"(b1));
}

__device__ __forceinline__ int hpack_idx(int p) {
    int s = p >> 3, r = p & 7;
    return (r < 4) ? (s * 4 + r) * 2 : (s * 4 + r - 4) * 2 + 1;
}

// ---------------------------------------------------------------------------
__device__ __forceinline__ void emit_w(const float* W, int Kp, int N, int RS,
                                       uint32_t* oh, uint32_t* ol, int i) {
    int row = i / N, n = i - row * N;
    int s = row >> 2, j = row & 3;
    int kp1 = 8 * s + j, kp2 = kp1 + 4;
    float a0 = 0.f, a1 = 0.f, c0 = 0.f, c1 = 0.f;
    if (kp1 < Kp) { a0 = W[(2 * kp1) * N + n]; a1 = W[(2 * kp1 + 1) * N + n]; }
    if (kp2 < Kp) { c0 = W[(2 * kp2) * N + n]; c1 = W[(2 * kp2 + 1) * N + n]; }
    uint32_t h1, l1, h2, l2;
    splitpack(a0, a1, h1, l1);
    splitpack(c0, c1, h2, l2);
    oh[row * RS + 2 * n] = h1; oh[row * RS + 2 * n + 1] = h2;
    ol[row * RS + 2 * n] = l1; ol[row * RS + 2 * n + 1] = l2;
}

__device__ __forceinline__ float cat_msg(const float* Wm, int k, int n) {
    return (n < 64) ? Wm[k * 64 + n] : Wm[(64 + k) * 64 + (n - 64)];
}
__device__ __forceinline__ float cat_eh(const float* W1, int k, int n) {
    return (n < 128) ? W1[k * 128 + n] : W1[(64 + k) * 128 + (n - 128)];
}

#define SW_U  (32*64)
#define SW_2  (32*64)
#define SW_PM (16*128)
#define SW_PE (16*256)
#define SW_TOTAL (SW_U + SW_2 + SW_PM + SW_PE)

__global__ void split_w_kernel(const float* __restrict__ Wu, const float* __restrict__ W2,
                               const float* __restrict__ Wm, const float* __restrict__ W1) {
    int i = blockIdx.x * 256 + threadIdx.x;
    if (i < SW_U) { emit_w(Wu, 64, 64, 136, g_Wu_h, g_Wu_l, i); return; }
    i -= SW_U;
    if (i < SW_2) { emit_w(W2, 64, 64, 136, g_W2_h, g_W2_l, i); return; }
    i -= SW_2;
    if (i < SW_PM) {
        int row = i >> 7, n = i & 127;
        int s = row >> 2, j = row & 3;
        int kp1 = 8 * s + j, kp2 = kp1 + 4;
        uint32_t h1, l1, h2, l2;
        splitpack(cat_msg(Wm, 2 * kp1, n), cat_msg(Wm, 2 * kp1 + 1, n), h1, l1);
        splitpack(cat_msg(Wm, 2 * kp2, n), cat_msg(Wm, 2 * kp2 + 1, n), h2, l2);
        g_Wpm_h[row * 256 + 2 * n] = h1; g_Wpm_h[row * 256 + 2 * n + 1] = h2;
        g_Wpm_l[row * 256 + 2 * n] = l1; g_Wpm_l[row * 256 + 2 * n + 1] = l2;
        return;
    }
    i -= SW_PM;
    if (i < SW_PE) {
        int row = i >> 8, n = i & 255;
        int s = row >> 2, j = row & 3;
        int kp1 = 8 * s + j, kp2 = kp1 + 4;
        uint32_t h1, l1, h2, l2;
        splitpack(cat_eh(W1, 2 * kp1, n), cat_eh(W1, 2 * kp1 + 1, n), h1, l1);
        splitpack(cat_eh(W1, 2 * kp2, n), cat_eh(W1, 2 * kp2 + 1, n), h2, l2);
        g_Wpe_h[row * 512 + 2 * n] = h1; g_Wpe_h[row * 512 + 2 * n + 1] = h2;
        g_Wpe_l[row * 512 + 2 * n] = l1; g_Wpe_l[row * 512 + 2 * n + 1] = l2;
    }
}

// ---------------------------------------------------------------------------
__global__ void enc_kernel(const float* __restrict__ x,
                           const float* __restrict__ W,
                           const float* __restrict__ b) {
    __shared__ float Ws[IND * H];
    __shared__ float bs[H];
    for (int i = threadIdx.x; i < IND * H; i += blockDim.x) Ws[i] = W[i];
    if (threadIdx.x < H) bs[threadIdx.x] = b[threadIdx.x];
    __syncthreads();
    int node = blockIdx.x * blockDim.x + threadIdx.x;
    if (node >= NN) return;
    float xv[IND];
#pragma unroll
    for (int k = 0; k < IND; k++) xv[k] = x[node * IND + k];
#pragma unroll 4
    for (int n = 0; n < H; n += 2) {
        float a0 = bs[n], a1 = bs[n + 1];
#pragma unroll
        for (int k = 0; k < IND; k++) {
            a0 += xv[k] * Ws[k * H + n];
            a1 += xv[k] * Ws[k * H + n + 1];
        }
        g_h[node * H + n] = a0;
        g_h[node * H + n + 1] = a1;
        uint32_t h, l;
        splitpack(a0, a1, h, l);
        int idx = hpack_idx(n >> 1);
        g_hh2[node * 32 + idx] = h;
        g_hl2[node * 32 + idx] = l;
    }
}

// ---------------------------------------------------------------------------
// proj: out[node][blockIdx.y*128 .. +128) = h_packed @ Wcat-block (K=64)
// Weight panel staged global->smem coalesced, then reg-copied (LDS).
// ---------------------------------------------------------------------------
#define HSTR 20
#define PROJ_SMEM (4160 * 8)   // 16 rows x 130 u2 x 2 planes = 33,280 B

__global__ void __launch_bounds__(256)
proj_kernel(int which) {
    extern __shared__ uint2 shp[];
    const uint2* WhG = which ? (const uint2*)g_Wpe_h : (const uint2*)g_Wpm_h;
    const uint2* WlG = which ? (const uint2*)g_Wpe_l : (const uint2*)g_Wpm_l;
    float* outp = which ? g_P1 : g_PQ;
    const int rs2 = which ? 256 : 128;     // uint2 per weight row
    const int ld = which ? 256 : 128;      // floats per output row
    const int nbase = blockIdx.x * 64;
    const int colbase = blockIdx.y * 128;
    const int tid = threadIdx.x;
    const int lane = tid & 31, warp = tid >> 5;
    const int g = lane >> 2, tig = lane & 3;
    const int warpM = warp & 3, warpN = warp >> 2;
    const int row0 = warpM * 16 + g;

    // stage weight panel (coalesced)
    for (int i = tid; i < 16 * 128; i += 256) {
        int r = i >> 7, cc = i & 127;
        shp[r * 130 + cc]        = WhG[r * rs2 + colbase + cc];
        shp[2080 + r * 130 + cc] = WlG[r * rs2 + colbase + cc];
    }
    __syncthreads();

    uint2 brh[4][8], brl[4][8];
#pragma unroll
    for (int s = 0; s < 4; s++)
#pragma unroll
        for (int nt = 0; nt < 8; nt++) {
            int idx = (s * 4 + tig) * 130 + warpN * 64 + nt * 8 + g;
            brh[s][nt] = shp[idx];
            brl[s][nt] = shp[2080 + idx];
        }
    __syncthreads();   // reg copies done before A overwrites

    uint2* Ah = shp;                 // 2560 u2 <= 4160
    uint2* Al = shp + 64 * HSTR;
    for (int i = tid; i < 64 * 16; i += 256) {
        int nd = i >> 4, u = i & 15;
        int gn = nbase + nd;
        uint2 h = make_uint2(0, 0), l = make_uint2(0, 0);
        if (gn < NN) {
            h = ((const uint2*)g_hh2)[gn * 16 + u];
            l = ((const uint2*)g_hl2)[gn * 16 + u];
        }
        Ah[nd * HSTR + u] = h;
        Al[nd * HSTR + u] = l;
    }
    __syncthreads();

    float acc[8][4] = {};
#pragma unroll
    for (int s = 0; s < 4; s++) {
        uint2 u0h = Ah[ row0      * HSTR + s * 4 + tig];
        uint2 u1h = Ah[(row0 + 8) * HSTR + s * 4 + tig];
        uint2 u0l = Al[ row0      * HSTR + s * 4 + tig];
        uint2 u1l = Al[(row0 + 8) * HSTR + s * 4 + tig];
        uint32_t ah[4] = {u0h.x, u1h.x, u0h.y, u1h.y};
        uint32_t al[4] = {u0l.x, u1l.x, u0l.y, u1l.y};
#pragma unroll
        for (int nt = 0; nt < 8; nt++) {
            mma_bf16(acc[nt], ah, brh[s][nt].x, brh[s][nt].y);
            mma_bf16(acc[nt], al, brh[s][nt].x, brh[s][nt].y);
            mma_bf16(acc[nt], ah, brl[s][nt].x, brl[s][nt].y);
        }
    }
    const int gn0 = nbase + row0, gn1 = gn0 + 8;
#pragma unroll
    for (int nt = 0; nt < 8; nt++) {
        int n = colbase + warpN * 64 + nt * 8 + 2 * tig;
        if (gn0 < NN) *(float2*)(outp + (size_t)gn0 * ld + n) = make_float2(acc[nt][0], acc[nt][1]);
        if (gn1 < NN) *(float2*)(outp + (size_t)gn1 * ld + n) = make_float2(acc[nt][2], acc[nt][3]);
    }
}

// ---------------------------------------------------------------------------
// msg edge pass (unchanged from R15; coalesced c = j*16 + q*4)
// ---------------------------------------------------------------------------
__global__ void __launch_bounds__(256)
edgepass_kernel(const int* __restrict__ ei, const float* __restrict__ ea,
                const float* __restrict__ Wm, const float* __restrict__ bm) {
    __shared__ float Wb[8 * 64];
    __shared__ float bs[64];
    for (int i = threadIdx.x; i < 512; i += 256) Wb[i] = Wm[(128 + (i >> 6)) * 64 + (i & 63)];
    if (threadIdx.x < 64) bs[threadIdx.x] = bm[threadIdx.x];
    __syncthreads();

    int idx = blockIdx.x * 256 + threadIdx.x;
    int e = idx >> 2, q = idx & 3;
    int s = ei[e], d = ei[EE + e];
    float av[8];
    {
        float4 a0 = *(const float4*)(ea + (size_t)e * 8);
        float4 a1 = *(const float4*)(ea + (size_t)e * 8 + 4);
        av[0] = a0.x; av[1] = a0.y; av[2] = a0.z; av[3] = a0.w;
        av[4] = a1.x; av[5] = a1.y; av[6] = a1.z; av[7] = a1.w;
    }
    const float* Pb = g_PQ + (size_t)s * 128;
    const float* Qb = g_PQ + (size_t)d * 128 + 64;
    float* ob = g_agg + d * 64;
#pragma unroll
    for (int j = 0; j < 4; j++) {
        int c = j * 16 + q * 4;
        float r0 = bs[c], r1 = bs[c + 1], r2 = bs[c + 2], r3 = bs[c + 3];
#pragma unroll
        for (int k = 0; k < 8; k++) {
            float a = av[k];
            r0 += a * Wb[k * 64 + c];
            r1 += a * Wb[k * 64 + c + 1];
            r2 += a * Wb[k * 64 + c + 2];
            r3 += a * Wb[k * 64 + c + 3];
        }
        float4 p  = *(const float4*)(Pb + c);
        float4 qq = *(const float4*)(Qb + c);
        float4 v = make_float4(fmaxf(p.x + qq.x + r0, 0.f),
                               fmaxf(p.y + qq.y + r1, 0.f),
                               fmaxf(p.z + qq.z + r2, 0.f),
                               fmaxf(p.w + qq.w + r3, 0.f));
        asm volatile("red.global.add.v4.f32 [%0], {%1,%2,%3,%4};"
                     :: "l"(ob + c), "f"(v.x), "f"(v.y), "f"(v.z), "f"(v.w) : "memory");
    }
}

// ---------------------------------------------------------------------------
// Update: h = relu([h|agg]@Wu + b); zeroes g_agg. Weights staged via smem.
// ---------------------------------------------------------------------------
#define ASLOT 36
#define UPD_SMEM (2 * 64 * ASLOT * 8)   // 36,864 B (also holds 34,816 B weight stage)

__global__ void __launch_bounds__(256, 1)
upd_kernel(const float* __restrict__ bias) {
    extern __shared__ uint2 smU[];
    const int nbase = blockIdx.x * 64;
    const int tid = threadIdx.x;
    const int lane = tid & 31, warp = tid >> 5;
    const int g = lane >> 2, tig = lane & 3;
    const int warpM = warp & 3, warpN = warp >> 2;
    const int row0 = warpM * 16 + g;

    // stage weight planes coalesced, then reg-copy
    for (int i = tid; i < 2176; i += 256) {
        smU[i]        = ((const uint2*)g_Wu_h)[i];
        smU[2176 + i] = ((const uint2*)g_Wu_l)[i];
    }
    __syncthreads();
    uint2 brh[8][4], brl[8][4];
#pragma unroll
    for (int s = 0; s < 8; s++)
#pragma unroll
        for (int nt = 0; nt < 4; nt++) {
            int idx = (s * 4 + tig) * 68 + warpN * 32 + nt * 8 + g;
            brh[s][nt] = smU[idx];
            brl[s][nt] = smU[2176 + idx];
        }
    __syncthreads();

    uint2* Ah = smU;
    uint2* Al = smU + 64 * ASLOT;
    for (int i = tid; i < 64 * 32; i += 256) {
        int nd = i >> 5, u = i & 31;
        int gn = nbase + nd;
        if (u < 16) {
            uint2 h = make_uint2(0, 0), l = make_uint2(0, 0);
            if (gn < NN) {
                h = ((const uint2*)g_hh2)[gn * 16 + u];
                l = ((const uint2*)g_hl2)[gn * 16 + u];
            }
            Ah[nd * ASLOT + u] = h;
            Al[nd * ASLOT + u] = l;
        } else {
            int s = u >> 2, j = u & 3;
            int pa1 = 8 * (s - 4) + j, pa2 = pa1 + 4;
            uint32_t h1 = 0, l1 = 0, h2 = 0, l2 = 0;
            if (gn < NN) {
                float2 v1 = *(float2*)(g_agg + gn * H + 2 * pa1);
                float2 v2 = *(float2*)(g_agg + gn * H + 2 * pa2);
                splitpack(v1.x, v1.y, h1, l1);
                splitpack(v2.x, v2.y, h2, l2);
                *(float2*)(g_agg + gn * H + 2 * pa1) = make_float2(0.f, 0.f);
                *(float2*)(g_agg + gn * H + 2 * pa2) = make_float2(0.f, 0.f);
            }
            Ah[nd * ASLOT + u] = make_uint2(h1, h2);
            Al[nd * ASLOT + u] = make_uint2(l1, l2);
        }
    }
    __syncthreads();

    float acc[4][4] = {};
#pragma unroll
    for (int s = 0; s < 8; s++) {
        uint2 u0h = Ah[ row0      * ASLOT + s * 4 + tig];
        uint2 u1h = Ah[(row0 + 8) * ASLOT + s * 4 + tig];
        uint2 u0l = Al[ row0      * ASLOT + s * 4 + tig];
        uint2 u1l = Al[(row0 + 8) * ASLOT + s * 4 + tig];
        uint32_t ah[4] = {u0h.x, u1h.x, u0h.y, u1h.y};
        uint32_t al[4] = {u0l.x, u1l.x, u0l.y, u1l.y};
#pragma unroll
        for (int nt = 0; nt < 4; nt++) {
            mma_bf16(acc[nt], ah, brh[s][nt].x, brh[s][nt].y);
            mma_bf16(acc[nt], al, brh[s][nt].x, brh[s][nt].y);
            mma_bf16(acc[nt], ah, brl[s][nt].x, brl[s][nt].y);
        }
    }

    const int gn0 = nbase + row0, gn1 = nbase + row0 + 8;
#pragma unroll
    for (int nt = 0; nt < 4; nt++) {
        int n = warpN * 32 + nt * 8 + 2 * tig;
        int p = n >> 1;
        int idx = hpack_idx(p);
        float bb0 = __ldg(bias + n), bb1 = __ldg(bias + n + 1);
        if (gn0 < NN) {
            float v0 = fmaxf(acc[nt][0] + bb0, 0.f);
            float v1 = fmaxf(acc[nt][1] + bb1, 0.f);
            *(float2*)(g_h + gn0 * H + n) = make_float2(v0, v1);
            splitpack(v0, v1, g_hh2[gn0 * 32 + idx], g_hl2[gn0 * 32 + idx]);
        }
        if (gn1 < NN) {
            float v0 = fmaxf(acc[nt][2] + bb0, 0.f);
            float v1 = fmaxf(acc[nt][3] + bb1, 0.f);
            *(float2*)(g_h + gn1 * H + n) = make_float2(v0, v1);
            splitpack(v0, v1, g_hh2[gn1 * 32 + idx], g_hl2[gn1 * 32 + idx]);
        }
    }
}

// ---------------------------------------------------------------------------
// Node head (FFMA, unchanged)
// ---------------------------------------------------------------------------
__global__ void __launch_bounds__(256)
nodehead_kernel(const float* __restrict__ W1, const float* __restrict__ b1,
                const float* __restrict__ W2, const float* __restrict__ b2,
                float* __restrict__ out) {
    __shared__ float As[64 * 64];
    __shared__ float Ws[64 * 64];
    __shared__ float W2s[64 * 2];
    __shared__ float b2s[2];
    int nbase = blockIdx.x * 64;

    for (int i = threadIdx.x; i < 64 * 64; i += 256) Ws[i] = W1[i];
    if (threadIdx.x < 128) W2s[threadIdx.x] = W2[threadIdx.x];
    if (threadIdx.x < 2) b2s[threadIdx.x] = b2[threadIdx.x];
    for (int i = threadIdx.x; i < 64 * 64; i += 256) {
        int nd = i >> 6, k = i & 63;
        int gn = nbase + nd;
        As[i] = (gn < NN) ? g_h[gn * H + k] : 0.f;
    }
    __syncthreads();

    int tn = threadIdx.x & 15, te = threadIdx.x >> 4;
    float acc[4][4] = {};
    for (int k = 0; k < 64; k += 4) {
        float4 av4[4];
#pragma unroll
        for (int i = 0; i < 4; i++)
            av4[i] = *(const float4*)(As + (te * 4 + i) * 64 + k);
        const float* av = (const float*)av4;
#pragma unroll
        for (int kk = 0; kk < 4; kk++) {
            float4 w = *(const float4*)(Ws + (k + kk) * H + tn * 4);
#pragma unroll
            for (int i = 0; i < 4; i++) {
                float a = av[i * 4 + kk];
                acc[i][0] += a * w.x;
                acc[i][1] += a * w.y;
                acc[i][2] += a * w.z;
                acc[i][3] += a * w.w;
            }
        }
    }
    __syncthreads();

    float4 bvv = *(const float4*)(b1 + tn * 4);
    const float* bvp = (const float*)&bvv;
#pragma unroll
    for (int i = 0; i < 4; i++)
#pragma unroll
        for (int j = 0; j < 4; j++)
            As[(tn * 4 + j) * 64 + te * 4 + i] = fmaxf(acc[i][j] + bvp[j], 0.f);
    __syncthreads();

    if (threadIdx.x < 128) {
        int nd = threadIdx.x & 63, j = threadIdx.x >> 6;
        int gn = nbase + nd;
        if (gn < NN) {
            float s = b2s[j];
#pragma unroll 8
            for (int k = 0; k < 64; k++) s += As[k * 64 + nd] * W2s[k * 2 + j];
            out[gn * 2 + j] = s;
        }
    }
}

// ---------------------------------------------------------------------------
// Edge head v4: persistent (2 blocks/SM), NO cp.async staging — phase 1 reads
// P1[src]/Q1[dst]/ea directly from global (coalesced c = 4q+16j). W2 in smem.
// smem (u32 words): W2h[0,4352) W2l[4352,8704) C1h[8704,13312) C1l[13312,17920)
//                   C2[17920,22080) W1b[22080,23104) b1[23104,23232)
//                   W3[23232,23616) b3[23616,23622)
// ---------------------------------------------------------------------------
#define NT_EH (EE / 64)
#define EH_GRID 296
#define EH_SMEM (23624 * 4)    // 94,496 B -> 2 blocks/SM

__global__ void __launch_bounds__(256, 2)
edgehead_kernel(const int* __restrict__ ei, const float* __restrict__ ea,
                const float* __restrict__ W1, const float* __restrict__ b1,
                const float* __restrict__ b2,
                const float* __restrict__ W3, const float* __restrict__ b3,
                float* __restrict__ out) {
    extern __shared__ uint32_t smW[];
    const int* src = ei;
    const int* dst = ei + EE;
    const int tid = threadIdx.x;

    // load W2 planes coalesced into smem
    for (int i = tid; i < 4352; i += 256) {
        smW[i]        = g_W2_h[i];
        smW[4352 + i] = g_W2_l[i];
    }
    float* W1b = (float*)(smW + 22080);
    float* b1s = (float*)(smW + 23104);
    float* W3s = (float*)(smW + 23232);
    float* b3s = (float*)(smW + 23616);
    for (int i = tid; i < 1024; i += 256) W1b[i] = W1[(128 + (i >> 7)) * 128 + (i & 127)];
    for (int i = tid; i < 128; i += 256) b1s[i] = b1[i];
    for (int i = tid; i < 384; i += 256) W3s[i] = W3[i];
    if (tid < 6) b3s[tid] = b3[tid];

    const int lane = tid & 31, warp = tid >> 5;
    const int g = lane >> 2, tig = lane & 3;
    const int warpM = warp & 3, warpN = warp >> 2;
    const int row0 = warpM * 16 + g;

    float2 b2v[4];
#pragma unroll
    for (int nt = 0; nt < 4; nt++) {
        int n = warpN * 32 + nt * 8 + 2 * tig;
        b2v[nt] = make_float2(__ldg(b2 + n), __ldg(b2 + n + 1));
    }
    __syncthreads();

    const uint2* W2h2 = (const uint2*)smW;
    const uint2* W2l2 = (const uint2*)(smW + 4352);
    uint32_t* C1h = smW + 8704;
    uint32_t* C1l = smW + 13312;
    const uint2* Ch2 = (const uint2*)C1h;
    const uint2* Cl2 = (const uint2*)C1l;
    float* C2 = (float*)(smW + 17920);

    const int e = tid >> 2, q = tid & 3;
    const int off0 = (q == 0) ? 0 : (q == 1) ? 4 : (q == 2) ? 1 : 5;
    const int off1 = off0 + 2;

    for (int t = blockIdx.x; t < NT_EH; t += EH_GRID) {
        const int ebase = t * 64;
        const int ge = ebase + e;

        // phase 1: C1 = relu(P1[src] + Q1[dst] + ea@W1bot + b1), direct global
        uint32_t c1h[16], c1l[16];
        {
            int s_ = src[ge], d_ = dst[ge];
            float av[8];
            float4 a0 = __ldg((const float4*)(ea + (size_t)ge * 8));
            float4 a1 = __ldg((const float4*)(ea + (size_t)ge * 8 + 4));
            av[0] = a0.x; av[1] = a0.y; av[2] = a0.z; av[3] = a0.w;
            av[4] = a1.x; av[5] = a1.y; av[6] = a1.z; av[7] = a1.w;
            const float* Pb = g_P1 + (size_t)s_ * 256;
            const float* Qb = g_P1 + (size_t)d_ * 256 + 128;
#pragma unroll
            for (int j = 0; j < 8; j++) {
                int c = 4 * q + 16 * j;
                float r0 = b1s[c], r1 = b1s[c + 1], r2 = b1s[c + 2], r3 = b1s[c + 3];
#pragma unroll
                for (int k = 0; k < 8; k++) {
                    float a = av[k];
                    r0 += a * W1b[k * 128 + c];
                    r1 += a * W1b[k * 128 + c + 1];
                    r2 += a * W1b[k * 128 + c + 2];
                    r3 += a * W1b[k * 128 + c + 3];
                }
                float4 p  = __ldg((const float4*)(Pb + c));
                float4 qq = __ldg((const float4*)(Qb + c));
                float v0 = fmaxf(p.x + qq.x + r0, 0.f);
                float v1 = fmaxf(p.y + qq.y + r1, 0.f);
                float v2 = fmaxf(p.z + qq.z + r2, 0.f);
                float v3 = fmaxf(p.w + qq.w + r3, 0.f);
                splitpack(v0, v1, c1h[2 * j], c1l[2 * j]);
                splitpack(v2, v3, c1h[2 * j + 1], c1l[2 * j + 1]);
            }
        }
        __syncthreads();   // A: prev tile's GEMM2/GEMM3 done with C1/C2

        // phase 2: write C1 planes (u32 stride 72)
        {
            uint32_t* bh = C1h + e * 72;
            uint32_t* bl = C1l + e * 72;
#pragma unroll
            for (int j = 0; j < 8; j++) {
                bh[8 * j + off0] = c1h[2 * j];
                bh[8 * j + off1] = c1h[2 * j + 1];
                bl[8 * j + off0] = c1l[2 * j];
                bl[8 * j + off1] = c1l[2 * j + 1];
            }
        }
        __syncthreads();   // B: C1 ready

        // phase 3: GEMM2 (bf16x3, W2 from smem) + C2 epilogue
        float acc2[4][4] = {};
#pragma unroll
        for (int s = 0; s < 8; s++) {
            uint2 u0h = Ch2[ row0      * 36 + s * 4 + tig];
            uint2 u1h = Ch2[(row0 + 8) * 36 + s * 4 + tig];
            uint2 u0l = Cl2[ row0      * 36 + s * 4 + tig];
            uint2 u1l = Cl2[(row0 + 8) * 36 + s * 4 + tig];
            uint32_t ah[4] = {u0h.x, u1h.x, u0h.y, u1h.y};
            uint32_t al[4] = {u0l.x, u1l.x, u0l.y, u1l.y};
#pragma unroll
            for (int nt = 0; nt < 4; nt++) {
                int bidx = (s * 4 + tig) * 68 + warpN * 32 + nt * 8 + g;
                uint2 bh = W2h2[bidx];
                uint2 bl = W2l2[bidx];
                mma_bf16(acc2[nt], ah, bh.x, bh.y);
                mma_bf16(acc2[nt], al, bh.x, bh.y);
                mma_bf16(acc2[nt], ah, bl.x, bl.y);
            }
        }
#pragma unroll
        for (int nt = 0; nt < 4; nt++) {
            int n = warpN * 32 + nt * 8 + 2 * tig;
            C2[ row0      * 65 + n    ] = fmaxf(acc2[nt][0] + b2v[nt].x, 0.f);
            C2[ row0      * 65 + n + 1] = fmaxf(acc2[nt][1] + b2v[nt].y, 0.f);
            C2[(row0 + 8) * 65 + n    ] = fmaxf(acc2[nt][2] + b2v[nt].x, 0.f);
            C2[(row0 + 8) * 65 + n + 1] = fmaxf(acc2[nt][3] + b2v[nt].y, 0.f);
        }
        __syncthreads();   // C: C2 ready

        // GEMM3: [64,64]@[64,6] -> out
        for (int w = tid; w < 384; w += 256) {
            int ee = w & 63, j = w >> 6;
            float s = b3s[j];
#pragma unroll 8
            for (int k = 0; k < 64; k++) s += C2[ee * 65 + k] * W3s[k * 6 + j];
            out[(ebase + ee) * 6 + j] = s;
        }
        // no trailing barrier: next phase1 touches no smem; barrier A protects
    }
}

// ---------------------------------------------------------------------------

extern "C" void kernel_launch(void* const* d_in, const int* in_sizes, int n_in,
                              void* d_out, int out_size) {
    const float* x     = (const float*)d_in[0];
    const int*   ei    = (const int*)d_in[1];
    const float* ea    = (const float*)d_in[2];
    const float* W_enc = (const float*)d_in[3];
    const float* b_enc = (const float*)d_in[4];
    const float* W_msg = (const float*)d_in[5];
    const float* b_msg = (const float*)d_in[6];
    const float* W_upd = (const float*)d_in[7];
    const float* b_upd = (const float*)d_in[8];
    const float* W_nd1 = (const float*)d_in[9];
    const float* b_nd1 = (const float*)d_in[10];
    const float* W_nd2 = (const float*)d_in[11];
    const float* b_nd2 = (const float*)d_in[12];
    const float* W_ed1 = (const float*)d_in[13];
    const float* b_ed1 = (const float*)d_in[14];
    const float* W_ed2 = (const float*)d_in[15];
    const float* b_ed2 = (const float*)d_in[16];
    const float* W_ed3 = (const float*)d_in[17];
    const float* b_ed3 = (const float*)d_in[18];
    float* out = (float*)d_out;

    cudaFuncSetAttribute(upd_kernel, cudaFuncAttributeMaxDynamicSharedMemorySize, UPD_SMEM);
    cudaFuncSetAttribute(edgehead_kernel, cudaFuncAttributeMaxDynamicSharedMemorySize, EH_SMEM);

    split_w_kernel<<<(SW_TOTAL + 255) / 256, 256>>>(W_upd, W_ed2, W_msg, W_ed1);
    enc_kernel<<<(NN + 255) / 256, 256>>>(x, W_enc, b_enc);

    dim3 pgm((NN + 63) / 64, 1);
    proj_kernel<<<pgm, 256, PROJ_SMEM>>>(0);
    for (int l = 0; l < 3; l++) {
        edgepass_kernel<<<EE * 4 / 256, 256>>>(ei, ea, W_msg, b_msg);
        upd_kernel<<<(NN + 63) / 64, 256, UPD_SMEM>>>(b_upd);
        if (l < 2) proj_kernel<<<pgm, 256, PROJ_SMEM>>>(0);
    }
    nodehead_kernel<<<(NN + 63) / 64, 256>>>(W_nd1, b_nd1, W_nd2, b_nd2, out);
    dim3 pge((NN + 63) / 64, 2);
    proj_kernel<<<pge, 256, PROJ_SMEM>>>(1);
    edgehead_kernel<<<EH_GRID, 256, EH_SMEM>>>(ei, ea, W_ed1, b_ed1, b_ed2,
                                               W_ed3, b_ed3, out + 2 * NN);
}

// round 17
// speedup vs baseline: 1.5114x; 1.0051x over previous
#include <cuda_runtime.h>
#include <cstdint>

#define NN 50000
#define EE 800000
#define IND 16
#define H 64
#define EAD 8

__device__ float g_h[NN * H];
__device__ float g_agg[NN * H];        // zero-init; re-zeroed by every upd round
__device__ uint32_t g_hh2[NN * 32];
__device__ uint32_t g_hl2[NN * 32];
__device__ float g_PQ[NN * 128];
__device__ float g_P1[NN * 256];

__device__ uint32_t g_Wu_h[32 * 136],  g_Wu_l[32 * 136];
__device__ uint32_t g_W2_h[32 * 136],  g_W2_l[32 * 136];
__device__ uint32_t g_Wpm_h[16 * 256], g_Wpm_l[16 * 256];
__device__ uint32_t g_Wpe_h[16 * 512], g_Wpe_l[16 * 512];

// ---------------------------------------------------------------------------
__device__ __forceinline__ void splitpack(float a0, float a1, uint32_t& hi, uint32_t& lo) {
    uint32_t h, l;
    asm("cvt.rn.bf16x2.f32 %0, %1, %2;" : "=r"(h) : "f"(a1), "f"(a0));
    float r0 = a0 - __uint_as_float(h << 16);
    float r1 = a1 - __uint_as_float(h & 0xFFFF0000u);
    asm("cvt.rn.bf16x2.f32 %0, %1, %2;" : "=r"(l) : "f"(r1), "f"(r0));
    hi = h; lo = l;
}

__device__ __forceinline__ void mma_bf16(float* c, const uint32_t* a, uint32_t b0, uint32_t b1) {
    asm volatile(
        "mma.sync.aligned.m16n8k16.row.col.f32.bf16.bf16.f32 "
        "{%0,%1,%2,%3}, {%4,%5,%6,%7}, {%8,%9}, {%0,%1,%2,%3};"
        : "+f"(c[0]), "+f"(c[1]), "+f"(c[2]), "+f"(c[3])
        : "r"(a[0]), "r"(a[1]), "r"(a[2]), "r"(a[3]), "r"(b0), "r"(b1));
}

__device__ __forceinline__ int hpack_idx(int p) {
    int s = p >> 3, r = p & 7;
    return (r < 4) ? (s * 4 + r) * 2 : (s * 4 + r - 4) * 2 + 1;
}

// ---------------------------------------------------------------------------
__device__ __forceinline__ void emit_w(const float* W, int Kp, int N, int RS,
                                       uint32_t* oh, uint32_t* ol, int i) {
    int row = i / N, n = i - row * N;
    int s = row >> 2, j = row & 3;
    int kp1 = 8 * s + j, kp2 = kp1 + 4;
    float a0 = 0.f, a1 = 0.f, c0 = 0.f, c1 = 0.f;
    if (kp1 < Kp) { a0 = W[(2 * kp1) * N + n]; a1 = W[(2 * kp1 + 1) * N + n]; }
    if (kp2 < Kp) { c0 = W[(2 * kp2) * N + n]; c1 = W[(2 * kp2 + 1) * N + n]; }
    uint32_t h1, l1, h2, l2;
    splitpack(a0, a1, h1, l1);
    splitpack(c0, c1, h2, l2);
    oh[row * RS + 2 * n] = h1; oh[row * RS + 2 * n + 1] = h2;
    ol[row * RS + 2 * n] = l1; ol[row * RS + 2 * n + 1] = l2;
}

__device__ __forceinline__ float cat_msg(const float* Wm, int k, int n) {
    return (n < 64) ? Wm[k * 64 + n] : Wm[(64 + k) * 64 + (n - 64)];
}
__device__ __forceinline__ float cat_eh(const float* W1, int k, int n) {
    return (n < 128) ? W1[k * 128 + n] : W1[(64 + k) * 128 + (n - 128)];
}

#define SW_U  (32*64)
#define SW_2  (32*64)
#define SW_PM (16*128)
#define SW_PE (16*256)
#define SW_TOTAL (SW_U + SW_2 + SW_PM + SW_PE)

__global__ void split_w_kernel(const float* __restrict__ Wu, const float* __restrict__ W2,
                               const float* __restrict__ Wm, const float* __restrict__ W1) {
    int i = blockIdx.x * 256 + threadIdx.x;
    if (i < SW_U) { emit_w(Wu, 64, 64, 136, g_Wu_h, g_Wu_l, i); return; }
    i -= SW_U;
    if (i < SW_2) { emit_w(W2, 64, 64, 136, g_W2_h, g_W2_l, i); return; }
    i -= SW_2;
    if (i < SW_PM) {
        int row = i >> 7, n = i & 127;
        int s = row >> 2, j = row & 3;
        int kp1 = 8 * s + j, kp2 = kp1 + 4;
        uint32_t h1, l1, h2, l2;
        splitpack(cat_msg(Wm, 2 * kp1, n), cat_msg(Wm, 2 * kp1 + 1, n), h1, l1);
        splitpack(cat_msg(Wm, 2 * kp2, n), cat_msg(Wm, 2 * kp2 + 1, n), h2, l2);
        g_Wpm_h[row * 256 + 2 * n] = h1; g_Wpm_h[row * 256 + 2 * n + 1] = h2;
        g_Wpm_l[row * 256 + 2 * n] = l1; g_Wpm_l[row * 256 + 2 * n + 1] = l2;
        return;
    }
    i -= SW_PM;
    if (i < SW_PE) {
        int row = i >> 8, n = i & 255;
        int s = row >> 2, j = row & 3;
        int kp1 = 8 * s + j, kp2 = kp1 + 4;
        uint32_t h1, l1, h2, l2;
        splitpack(cat_eh(W1, 2 * kp1, n), cat_eh(W1, 2 * kp1 + 1, n), h1, l1);
        splitpack(cat_eh(W1, 2 * kp2, n), cat_eh(W1, 2 * kp2 + 1, n), h2, l2);
        g_Wpe_h[row * 512 + 2 * n] = h1; g_Wpe_h[row * 512 + 2 * n + 1] = h2;
        g_Wpe_l[row * 512 + 2 * n] = l1; g_Wpe_l[row * 512 + 2 * n + 1] = l2;
    }
}

// ---------------------------------------------------------------------------
__global__ void enc_kernel(const float* __restrict__ x,
                           const float* __restrict__ W,
                           const float* __restrict__ b) {
    __shared__ float Ws[IND * H];
    __shared__ float bs[H];
    for (int i = threadIdx.x; i < IND * H; i += blockDim.x) Ws[i] = W[i];
    if (threadIdx.x < H) bs[threadIdx.x] = b[threadIdx.x];
    __syncthreads();
    int node = blockIdx.x * blockDim.x + threadIdx.x;
    if (node >= NN) return;
    float xv[IND];
#pragma unroll
    for (int k = 0; k < IND; k++) xv[k] = x[node * IND + k];
#pragma unroll 4
    for (int n = 0; n < H; n += 2) {
        float a0 = bs[n], a1 = bs[n + 1];
#pragma unroll
        for (int k = 0; k < IND; k++) {
            a0 += xv[k] * Ws[k * H + n];
            a1 += xv[k] * Ws[k * H + n + 1];
        }
        g_h[node * H + n] = a0;
        g_h[node * H + n + 1] = a1;
        uint32_t h, l;
        splitpack(a0, a1, h, l);
        int idx = hpack_idx(n >> 1);
        g_hh2[node * 32 + idx] = h;
        g_hl2[node * 32 + idx] = l;
    }
}

// ---------------------------------------------------------------------------
// proj (standalone; used once after enc): PQ = h_packed @ Wpm
// ---------------------------------------------------------------------------
#define HSTR 20
#define PROJ_SMEM (4160 * 8)

__global__ void __launch_bounds__(256)
proj_kernel() {
    extern __shared__ uint2 shp[];
    const uint2* WhG = (const uint2*)g_Wpm_h;
    const uint2* WlG = (const uint2*)g_Wpm_l;
    const int nbase = blockIdx.x * 64;
    const int tid = threadIdx.x;
    const int lane = tid & 31, warp = tid >> 5;
    const int g = lane >> 2, tig = lane & 3;
    const int warpM = warp & 3, warpN = warp >> 2;
    const int row0 = warpM * 16 + g;

    for (int i = tid; i < 16 * 128; i += 256) {
        int r = i >> 7, cc = i & 127;
        shp[r * 130 + cc]        = WhG[r * 128 + cc];
        shp[2080 + r * 130 + cc] = WlG[r * 128 + cc];
    }
    __syncthreads();

    uint2 brh[4][8], brl[4][8];
#pragma unroll
    for (int s = 0; s < 4; s++)
#pragma unroll
        for (int nt = 0; nt < 8; nt++) {
            int idx = (s * 4 + tig) * 130 + warpN * 64 + nt * 8 + g;
            brh[s][nt] = shp[idx];
            brl[s][nt] = shp[2080 + idx];
        }
    __syncthreads();

    uint2* Ah = shp;
    uint2* Al = shp + 64 * HSTR;
    for (int i = tid; i < 64 * 16; i += 256) {
        int nd = i >> 4, u = i & 15;
        int gn = nbase + nd;
        uint2 h = make_uint2(0, 0), l = make_uint2(0, 0);
        if (gn < NN) {
            h = ((const uint2*)g_hh2)[gn * 16 + u];
            l = ((const uint2*)g_hl2)[gn * 16 + u];
        }
        Ah[nd * HSTR + u] = h;
        Al[nd * HSTR + u] = l;
    }
    __syncthreads();

    float acc[8][4] = {};
#pragma unroll
    for (int s = 0; s < 4; s++) {
        uint2 u0h = Ah[ row0      * HSTR + s * 4 + tig];
        uint2 u1h = Ah[(row0 + 8) * HSTR + s * 4 + tig];
        uint2 u0l = Al[ row0      * HSTR + s * 4 + tig];
        uint2 u1l = Al[(row0 + 8) * HSTR + s * 4 + tig];
        uint32_t ah[4] = {u0h.x, u1h.x, u0h.y, u1h.y};
        uint32_t al[4] = {u0l.x, u1l.x, u0l.y, u1l.y};
#pragma unroll
        for (int nt = 0; nt < 8; nt++) {
            mma_bf16(acc[nt], ah, brh[s][nt].x, brh[s][nt].y);
            mma_bf16(acc[nt], al, brh[s][nt].x, brh[s][nt].y);
            mma_bf16(acc[nt], ah, brl[s][nt].x, brl[s][nt].y);
        }
    }
    const int gn0 = nbase + row0, gn1 = gn0 + 8;
#pragma unroll
    for (int nt = 0; nt < 8; nt++) {
        int n = warpN * 64 + nt * 8 + 2 * tig;
        if (gn0 < NN) *(float2*)(g_PQ + (size_t)gn0 * 128 + n) = make_float2(acc[nt][0], acc[nt][1]);
        if (gn1 < NN) *(float2*)(g_PQ + (size_t)gn1 * 128 + n) = make_float2(acc[nt][2], acc[nt][3]);
    }
}

// ---------------------------------------------------------------------------
// msg edge pass (coalesced c = j*16 + q*4)
// ---------------------------------------------------------------------------
__global__ void __launch_bounds__(256)
edgepass_kernel(const int* __restrict__ ei, const float* __restrict__ ea,
                const float* __restrict__ Wm, const float* __restrict__ bm) {
    __shared__ float Wb[8 * 64];
    __shared__ float bs[64];
    for (int i = threadIdx.x; i < 512; i += 256) Wb[i] = Wm[(128 + (i >> 6)) * 64 + (i & 63)];
    if (threadIdx.x < 64) bs[threadIdx.x] = bm[threadIdx.x];
    __syncthreads();

    int idx = blockIdx.x * 256 + threadIdx.x;
    int e = idx >> 2, q = idx & 3;
    int s = ei[e], d = ei[EE + e];
    float av[8];
    {
        float4 a0 = *(const float4*)(ea + (size_t)e * 8);
        float4 a1 = *(const float4*)(ea + (size_t)e * 8 + 4);
        av[0] = a0.x; av[1] = a0.y; av[2] = a0.z; av[3] = a0.w;
        av[4] = a1.x; av[5] = a1.y; av[6] = a1.z; av[7] = a1.w;
    }
    const float* Pb = g_PQ + (size_t)s * 128;
    const float* Qb = g_PQ + (size_t)d * 128 + 64;
    float* ob = g_agg + d * 64;
#pragma unroll
    for (int j = 0; j < 4; j++) {
        int c = j * 16 + q * 4;
        float r0 = bs[c], r1 = bs[c + 1], r2 = bs[c + 2], r3 = bs[c + 3];
#pragma unroll
        for (int k = 0; k < 8; k++) {
            float a = av[k];
            r0 += a * Wb[k * 64 + c];
            r1 += a * Wb[k * 64 + c + 1];
            r2 += a * Wb[k * 64 + c + 2];
            r3 += a * Wb[k * 64 + c + 3];
        }
        float4 p  = *(const float4*)(Pb + c);
        float4 qq = *(const float4*)(Qb + c);
        float4 v = make_float4(fmaxf(p.x + qq.x + r0, 0.f),
                               fmaxf(p.y + qq.y + r1, 0.f),
                               fmaxf(p.z + qq.z + r2, 0.f),
                               fmaxf(p.w + qq.w + r3, 0.f));
        asm volatile("red.global.add.v4.f32 [%0], {%1,%2,%3,%4};"
                     :: "l"(ob + c), "f"(v.x), "f"(v.y), "f"(v.z), "f"(v.w) : "memory");
    }
}

// ---------------------------------------------------------------------------
// FUSED update + projection:
//   h = relu([h|agg]@Wu + b)   (zeroes g_agg, writes g_h + packed h)
//   then PQ = h @ Wpm (which=0) or P1 = h @ Wpe (which=1), A from smem.
// smem (u2): A[0,4608) ; Wstage[4608, 4608+8256)
// ---------------------------------------------------------------------------
#define ASLOT 36
#define WOFF 4608
#define UPDPROJ_SMEM ((4608 + 8256) * 8)   // 102,912 B

__global__ void __launch_bounds__(256, 1)
updproj_kernel(const float* __restrict__ bias, int which) {
    extern __shared__ uint2 smU[];
    uint2* Wst = smU + WOFF;
    const int nbase = blockIdx.x * 64;
    const int tid = threadIdx.x;
    const int lane = tid & 31, warp = tid >> 5;
    const int g = lane >> 2, tig = lane & 3;
    const int warpM = warp & 3, warpN = warp >> 2;
    const int row0 = warpM * 16 + g;

    // 1. stage Wu planes coalesced (hi [0,2176), lo [2176,4352))
    for (int i = tid; i < 2176; i += 256) {
        Wst[i]        = ((const uint2*)g_Wu_h)[i];
        Wst[2176 + i] = ((const uint2*)g_Wu_l)[i];
    }
    __syncthreads();
    uint2 brh[8][4], brl[8][4];
#pragma unroll
    for (int s = 0; s < 8; s++)
#pragma unroll
        for (int nt = 0; nt < 4; nt++) {
            int idx = (s * 4 + tig) * 68 + warpN * 32 + nt * 8 + g;
            brh[s][nt] = Wst[idx];
            brl[s][nt] = Wst[2176 + idx];
        }
    __syncthreads();   // reg copies done; Wst free

    // 2. stage A (h|agg packed) + stage proj weights
    uint2* Ah = smU;
    uint2* Al = smU + 64 * ASLOT;
    for (int i = tid; i < 64 * 32; i += 256) {
        int nd = i >> 5, u = i & 31;
        int gn = nbase + nd;
        if (u < 16) {
            uint2 h = make_uint2(0, 0), l = make_uint2(0, 0);
            if (gn < NN) {
                h = ((const uint2*)g_hh2)[gn * 16 + u];
                l = ((const uint2*)g_hl2)[gn * 16 + u];
            }
            Ah[nd * ASLOT + u] = h;
            Al[nd * ASLOT + u] = l;
        } else {
            int s = u >> 2, j = u & 3;
            int pa1 = 8 * (s - 4) + j, pa2 = pa1 + 4;
            uint32_t h1 = 0, l1 = 0, h2 = 0, l2 = 0;
            if (gn < NN) {
                float2 v1 = *(float2*)(g_agg + gn * H + 2 * pa1);
                float2 v2 = *(float2*)(g_agg + gn * H + 2 * pa2);
                splitpack(v1.x, v1.y, h1, l1);
                splitpack(v2.x, v2.y, h2, l2);
                *(float2*)(g_agg + gn * H + 2 * pa1) = make_float2(0.f, 0.f);
                *(float2*)(g_agg + gn * H + 2 * pa2) = make_float2(0.f, 0.f);
            }
            Ah[nd * ASLOT + u] = make_uint2(h1, h2);
            Al[nd * ASLOT + u] = make_uint2(l1, l2);
        }
    }
    if (which == 0) {          // Wpm: 16 rows x 128 u2; smem stride 130; lo at 2080
        const uint2* GH = (const uint2*)g_Wpm_h;
        const uint2* GL = (const uint2*)g_Wpm_l;
        for (int i = tid; i < 2048; i += 256) {
            int r = i >> 7, cc = i & 127;
            Wst[r * 130 + cc]        = GH[r * 128 + cc];
            Wst[2080 + r * 130 + cc] = GL[r * 128 + cc];
        }
    } else {                   // Wpe: 16 rows x 256 u2; smem stride 258; lo at 4128
        const uint2* GH = (const uint2*)g_Wpe_h;
        const uint2* GL = (const uint2*)g_Wpe_l;
        for (int i = tid; i < 4096; i += 256) {
            int r = i >> 8, cc = i & 255;
            Wst[r * 258 + cc]        = GH[r * 256 + cc];
            Wst[4128 + r * 258 + cc] = GL[r * 256 + cc];
        }
    }
    __syncthreads();

    // 3. upd MMA
    float acc[4][4] = {};
#pragma unroll
    for (int s = 0; s < 8; s++) {
        uint2 u0h = Ah[ row0      * ASLOT + s * 4 + tig];
        uint2 u1h = Ah[(row0 + 8) * ASLOT + s * 4 + tig];
        uint2 u0l = Al[ row0      * ASLOT + s * 4 + tig];
        uint2 u1l = Al[(row0 + 8) * ASLOT + s * 4 + tig];
        uint32_t ah[4] = {u0h.x, u1h.x, u0h.y, u1h.y};
        uint32_t al[4] = {u0l.x, u1l.x, u0l.y, u1l.y};
#pragma unroll
        for (int nt = 0; nt < 4; nt++) {
            mma_bf16(acc[nt], ah, brh[s][nt].x, brh[s][nt].y);
            mma_bf16(acc[nt], al, brh[s][nt].x, brh[s][nt].y);
            mma_bf16(acc[nt], ah, brl[s][nt].x, brl[s][nt].y);
        }
    }
    __syncthreads();   // all A reads done before epilogue overwrites slots 0..15

    // 4. epilogue: write g_h, packed h (global + smem A slots 0..15)
    const int gn0 = nbase + row0, gn1 = nbase + row0 + 8;
    uint32_t* Ah32 = (uint32_t*)Ah;
    uint32_t* Al32 = (uint32_t*)Al;
#pragma unroll
    for (int nt = 0; nt < 4; nt++) {
        int n = warpN * 32 + nt * 8 + 2 * tig;
        int p = n >> 1;
        int idx = hpack_idx(p);
        float bb0 = __ldg(bias + n), bb1 = __ldg(bias + n + 1);
        {
            float v0 = fmaxf(acc[nt][0] + bb0, 0.f);
            float v1 = fmaxf(acc[nt][1] + bb1, 0.f);
            uint32_t h, l;
            splitpack(v0, v1, h, l);
            if (gn0 < NN) {
                *(float2*)(g_h + gn0 * H + n) = make_float2(v0, v1);
                g_hh2[gn0 * 32 + idx] = h;
                g_hl2[gn0 * 32 + idx] = l;
            }
            Ah32[row0 * 72 + idx] = h;
            Al32[row0 * 72 + idx] = l;
        }
        {
            float v0 = fmaxf(acc[nt][2] + bb0, 0.f);
            float v1 = fmaxf(acc[nt][3] + bb1, 0.f);
            uint32_t h, l;
            splitpack(v0, v1, h, l);
            if (gn1 < NN) {
                *(float2*)(g_h + gn1 * H + n) = make_float2(v0, v1);
                g_hh2[gn1 * 32 + idx] = h;
                g_hl2[gn1 * 32 + idx] = l;
            }
            Ah32[(row0 + 8) * 72 + idx] = h;
            Al32[(row0 + 8) * 72 + idx] = l;
        }
    }
    __syncthreads();

    // 5. proj MMA from smem A (slots 0..15) x smem Wst
    if (which == 0) {
        float pacc[8][4] = {};
#pragma unroll
        for (int s = 0; s < 4; s++) {
            uint2 u0h = Ah[ row0      * ASLOT + s * 4 + tig];
            uint2 u1h = Ah[(row0 + 8) * ASLOT + s * 4 + tig];
            uint2 u0l = Al[ row0      * ASLOT + s * 4 + tig];
            uint2 u1l = Al[(row0 + 8) * ASLOT + s * 4 + tig];
            uint32_t ah[4] = {u0h.x, u1h.x, u0h.y, u1h.y};
            uint32_t al[4] = {u0l.x, u1l.x, u0l.y, u1l.y};
#pragma unroll
            for (int nt = 0; nt < 8; nt++) {
                int widx = (s * 4 + tig) * 130 + warpN * 64 + nt * 8 + g;
                uint2 bh = Wst[widx];
                uint2 bl = Wst[2080 + widx];
                mma_bf16(pacc[nt], ah, bh.x, bh.y);
                mma_bf16(pacc[nt], al, bh.x, bh.y);
                mma_bf16(pacc[nt], ah, bl.x, bl.y);
            }
        }
#pragma unroll
        for (int nt = 0; nt < 8; nt++) {
            int n = warpN * 64 + nt * 8 + 2 * tig;
            if (gn0 < NN) *(float2*)(g_PQ + (size_t)gn0 * 128 + n) = make_float2(pacc[nt][0], pacc[nt][1]);
            if (gn1 < NN) *(float2*)(g_PQ + (size_t)gn1 * 128 + n) = make_float2(pacc[nt][2], pacc[nt][3]);
        }
    } else {
        float pacc[16][4] = {};
#pragma unroll
        for (int s = 0; s < 4; s++) {
            uint2 u0h = Ah[ row0      * ASLOT + s * 4 + tig];
            uint2 u1h = Ah[(row0 + 8) * ASLOT + s * 4 + tig];
            uint2 u0l = Al[ row0      * ASLOT + s * 4 + tig];
            uint2 u1l = Al[(row0 + 8) * ASLOT + s * 4 + tig];
            uint32_t ah[4] = {u0h.x, u1h.x, u0h.y, u1h.y};
            uint32_t al[4] = {u0l.x, u1l.x, u0l.y, u1l.y};
#pragma unroll
            for (int nt = 0; nt < 16; nt++) {
                int widx = (s * 4 + tig) * 258 + warpN * 128 + nt * 8 + g;
                uint2 bh = Wst[widx];
                uint2 bl = Wst[4128 + widx];
                mma_bf16(pacc[nt], ah, bh.x, bh.y);
                mma_bf16(pacc[nt], al, bh.x, bh.y);
                mma_bf16(pacc[nt], ah, bl.x, bl.y);
            }
        }
#pragma unroll
        for (int nt = 0; nt < 16; nt++) {
            int n = warpN * 128 + nt * 8 + 2 * tig;
            if (gn0 < NN) *(float2*)(g_P1 + (size_t)gn0 * 256 + n) = make_float2(pacc[nt][0], pacc[nt][1]);
            if (gn1 < NN) *(float2*)(g_P1 + (size_t)gn1 * 256 + n) = make_float2(pacc[nt][2], pacc[nt][3]);
        }
    }
}

// ---------------------------------------------------------------------------
// Node head (FFMA)
// ---------------------------------------------------------------------------
__global__ void __launch_bounds__(256)
nodehead_kernel(const float* __restrict__ W1, const float* __restrict__ b1,
                const float* __restrict__ W2, const float* __restrict__ b2,
                float* __restrict__ out) {
    __shared__ float As[64 * 64];
    __shared__ float Ws[64 * 64];
    __shared__ float W2s[64 * 2];
    __shared__ float b2s[2];
    int nbase = blockIdx.x * 64;

    for (int i = threadIdx.x; i < 64 * 64; i += 256) Ws[i] = W1[i];
    if (threadIdx.x < 128) W2s[threadIdx.x] = W2[threadIdx.x];
    if (threadIdx.x < 2) b2s[threadIdx.x] = b2[threadIdx.x];
    for (int i = threadIdx.x; i < 64 * 64; i += 256) {
        int nd = i >> 6, k = i & 63;
        int gn = nbase + nd;
        As[i] = (gn < NN) ? g_h[gn * H + k] : 0.f;
    }
    __syncthreads();

    int tn = threadIdx.x & 15, te = threadIdx.x >> 4;
    float acc[4][4] = {};
    for (int k = 0; k < 64; k += 4) {
        float4 av4[4];
#pragma unroll
        for (int i = 0; i < 4; i++)
            av4[i] = *(const float4*)(As + (te * 4 + i) * 64 + k);
        const float* av = (const float*)av4;
#pragma unroll
        for (int kk = 0; kk < 4; kk++) {
            float4 w = *(const float4*)(Ws + (k + kk) * H + tn * 4);
#pragma unroll
            for (int i = 0; i < 4; i++) {
                float a = av[i * 4 + kk];
                acc[i][0] += a * w.x;
                acc[i][1] += a * w.y;
                acc[i][2] += a * w.z;
                acc[i][3] += a * w.w;
            }
        }
    }
    __syncthreads();

    float4 bvv = *(const float4*)(b1 + tn * 4);
    const float* bvp = (const float*)&bvv;
#pragma unroll
    for (int i = 0; i < 4; i++)
#pragma unroll
        for (int j = 0; j < 4; j++)
            As[(tn * 4 + j) * 64 + te * 4 + i] = fmaxf(acc[i][j] + bvp[j], 0.f);
    __syncthreads();

    if (threadIdx.x < 128) {
        int nd = threadIdx.x & 63, j = threadIdx.x >> 6;
        int gn = nbase + nd;
        if (gn < NN) {
            float s = b2s[j];
#pragma unroll 8
            for (int k = 0; k < 64; k++) s += As[k * 64 + nd] * W2s[k * 2 + j];
            out[gn * 2 + j] = s;
        }
    }
}

// ---------------------------------------------------------------------------
// Edge head v4 (unchanged from R16): persistent, 2 blocks/SM, direct-global
// phase 1, W2 in smem.
// ---------------------------------------------------------------------------
#define NT_EH (EE / 64)
#define EH_GRID 296
#define EH_SMEM (23624 * 4)

__global__ void __launch_bounds__(256, 2)
edgehead_kernel(const int* __restrict__ ei, const float* __restrict__ ea,
                const float* __restrict__ W1, const float* __restrict__ b1,
                const float* __restrict__ b2,
                const float* __restrict__ W3, const float* __restrict__ b3,
                float* __restrict__ out) {
    extern __shared__ uint32_t smW[];
    const int* src = ei;
    const int* dst = ei + EE;
    const int tid = threadIdx.x;

    for (int i = tid; i < 4352; i += 256) {
        smW[i]        = g_W2_h[i];
        smW[4352 + i] = g_W2_l[i];
    }
    float* W1b = (float*)(smW + 22080);
    float* b1s = (float*)(smW + 23104);
    float* W3s = (float*)(smW + 23232);
    float* b3s = (float*)(smW + 23616);
    for (int i = tid; i < 1024; i += 256) W1b[i] = W1[(128 + (i >> 7)) * 128 + (i & 127)];
    for (int i = tid; i < 128; i += 256) b1s[i] = b1[i];
    for (int i = tid; i < 384; i += 256) W3s[i] = W3[i];
    if (tid < 6) b3s[tid] = b3[tid];

    const int lane = tid & 31, warp = tid >> 5;
    const int g = lane >> 2, tig = lane & 3;
    const int warpM = warp & 3, warpN = warp >> 2;
    const int row0 = warpM * 16 + g;

    float2 b2v[4];
#pragma unroll
    for (int nt = 0; nt < 4; nt++) {
        int n = warpN * 32 + nt * 8 + 2 * tig;
        b2v[nt] = make_float2(__ldg(b2 + n), __ldg(b2 + n + 1));
    }
    __syncthreads();

    const uint2* W2h2 = (const uint2*)smW;
    const uint2* W2l2 = (const uint2*)(smW + 4352);
    uint32_t* C1h = smW + 8704;
    uint32_t* C1l = smW + 13312;
    const uint2* Ch2 = (const uint2*)C1h;
    const uint2* Cl2 = (const uint2*)C1l;
    float* C2 = (float*)(smW + 17920);

    const int e = tid >> 2, q = tid & 3;
    const int off0 = (q == 0) ? 0 : (q == 1) ? 4 : (q == 2) ? 1 : 5;
    const int off1 = off0 + 2;

    for (int t = blockIdx.x; t < NT_EH; t += EH_GRID) {
        const int ebase = t * 64;
        const int ge = ebase + e;

        uint32_t c1h[16], c1l[16];
        {
            int s_ = src[ge], d_ = dst[ge];
            float av[8];
            float4 a0 = __ldg((const float4*)(ea + (size_t)ge * 8));
            float4 a1 = __ldg((const float4*)(ea + (size_t)ge * 8 + 4));
            av[0] = a0.x; av[1] = a0.y; av[2] = a0.z; av[3] = a0.w;
            av[4] = a1.x; av[5] = a1.y; av[6] = a1.z; av[7] = a1.w;
            const float* Pb = g_P1 + (size_t)s_ * 256;
            const float* Qb = g_P1 + (size_t)d_ * 256 + 128;
#pragma unroll
            for (int j = 0; j < 8; j++) {
                int c = 4 * q + 16 * j;
                float r0 = b1s[c], r1 = b1s[c + 1], r2 = b1s[c + 2], r3 = b1s[c + 3];
#pragma unroll
                for (int k = 0; k < 8; k++) {
                    float a = av[k];
                    r0 += a * W1b[k * 128 + c];
                    r1 += a * W1b[k * 128 + c + 1];
                    r2 += a * W1b[k * 128 + c + 2];
                    r3 += a * W1b[k * 128 + c + 3];
                }
                float4 p  = __ldg((const float4*)(Pb + c));
                float4 qq = __ldg((const float4*)(Qb + c));
                float v0 = fmaxf(p.x + qq.x + r0, 0.f);
                float v1 = fmaxf(p.y + qq.y + r1, 0.f);
                float v2 = fmaxf(p.z + qq.z + r2, 0.f);
                float v3 = fmaxf(p.w + qq.w + r3, 0.f);
                splitpack(v0, v1, c1h[2 * j], c1l[2 * j]);
                splitpack(v2, v3, c1h[2 * j + 1], c1l[2 * j + 1]);
            }
        }
        __syncthreads();

        {
            uint32_t* bh = C1h + e * 72;
            uint32_t* bl = C1l + e * 72;
#pragma unroll
            for (int j = 0; j < 8; j++) {
                bh[8 * j + off0] = c1h[2 * j];
                bh[8 * j + off1] = c1h[2 * j + 1];
                bl[8 * j + off0] = c1l[2 * j];
                bl[8 * j + off1] = c1l[2 * j + 1];
            }
        }
        __syncthreads();

        float acc2[4][4] = {};
#pragma unroll
        for (int s = 0; s < 8; s++) {
            uint2 u0h = Ch2[ row0      * 36 + s * 4 + tig];
            uint2 u1h = Ch2[(row0 + 8) * 36 + s * 4 + tig];
            uint2 u0l = Cl2[ row0      * 36 + s * 4 + tig];
            uint2 u1l = Cl2[(row0 + 8) * 36 + s * 4 + tig];
            uint32_t ah[4] = {u0h.x, u1h.x, u0h.y, u1h.y};
            uint32_t al[4] = {u0l.x, u1l.x, u0l.y, u1l.y};
#pragma unroll
            for (int nt = 0; nt < 4; nt++) {
                int bidx = (s * 4 + tig) * 68 + warpN * 32 + nt * 8 + g;
                uint2 bh = W2h2[bidx];
                uint2 bl = W2l2[bidx];
                mma_bf16(acc2[nt], ah, bh.x, bh.y);
                mma_bf16(acc2[nt], al, bh.x, bh.y);
                mma_bf16(acc2[nt], ah, bl.x, bl.y);
            }
        }
#pragma unroll
        for (int nt = 0; nt < 4; nt++) {
            int n = warpN * 32 + nt * 8 + 2 * tig;
            C2[ row0      * 65 + n    ] = fmaxf(acc2[nt][0] + b2v[nt].x, 0.f);
            C2[ row0      * 65 + n + 1] = fmaxf(acc2[nt][1] + b2v[nt].y, 0.f);
            C2[(row0 + 8) * 65 + n    ] = fmaxf(acc2[nt][2] + b2v[nt].x, 0.f);
            C2[(row0 + 8) * 65 + n + 1] = fmaxf(acc2[nt][3] + b2v[nt].y, 0.f);
        }
        __syncthreads();

        for (int w = tid; w < 384; w += 256) {
            int ee = w & 63, j = w >> 6;
            float s = b3s[j];
#pragma unroll 8
            for (int k = 0; k < 64; k++) s += C2[ee * 65 + k] * W3s[k * 6 + j];
            out[(ebase + ee) * 6 + j] = s;
        }
    }
}

// ---------------------------------------------------------------------------

extern "C" void kernel_launch(void* const* d_in, const int* in_sizes, int n_in,
                              void* d_out, int out_size) {
    const float* x     = (const float*)d_in[0];
    const int*   ei    = (const int*)d_in[1];
    const float* ea    = (const float*)d_in[2];
    const float* W_enc = (const float*)d_in[3];
    const float* b_enc = (const float*)d_in[4];
    const float* W_msg = (const float*)d_in[5];
    const float* b_msg = (const float*)d_in[6];
    const float* W_upd = (const float*)d_in[7];
    const float* b_upd = (const float*)d_in[8];
    const float* W_nd1 = (const float*)d_in[9];
    const float* b_nd1 = (const float*)d_in[10];
    const float* W_nd2 = (const float*)d_in[11];
    const float* b_nd2 = (const float*)d_in[12];
    const float* W_ed1 = (const float*)d_in[13];
    const float* b_ed1 = (const float*)d_in[14];
    const float* W_ed2 = (const float*)d_in[15];
    const float* b_ed2 = (const float*)d_in[16];
    const float* W_ed3 = (const float*)d_in[17];
    const float* b_ed3 = (const float*)d_in[18];
    float* out = (float*)d_out;

    cudaFuncSetAttribute(updproj_kernel, cudaFuncAttributeMaxDynamicSharedMemorySize, UPDPROJ_SMEM);
    cudaFuncSetAttribute(edgehead_kernel, cudaFuncAttributeMaxDynamicSharedMemorySize, EH_SMEM);

    split_w_kernel<<<(SW_TOTAL + 255) / 256, 256>>>(W_upd, W_ed2, W_msg, W_ed1);
    enc_kernel<<<(NN + 255) / 256, 256>>>(x, W_enc, b_enc);
    proj_kernel<<<(NN + 63) / 64, 256, PROJ_SMEM>>>();
    for (int l = 0; l < 3; l++) {
        edgepass_kernel<<<EE * 4 / 256, 256>>>(ei, ea, W_msg, b_msg);
        updproj_kernel<<<(NN + 63) / 64, 256, UPDPROJ_SMEM>>>(b_upd, l == 2 ? 1 : 0);
    }
    nodehead_kernel<<<(NN + 63) / 64, 256>>>(W_nd1, b_nd1, W_nd2, b_nd2, out);
    edgehead_kernel<<<EH_GRID, 256, EH_SMEM>>>(ei, ea, W_ed1, b_ed1, b_ed2,
                                               W_ed3, b_ed3, out + 2 * NN);
}